// round 15
// baseline (speedup 1.0000x reference)
#include <cuda_runtime.h>
#include <cstdint>
#include <cstddef>

#define Bd 4
#define Sd 1024
#define Dd 1024
#define Hd 16
#define DHd 64
#define Md (Bd*Sd)
#define OUT_OFF ((size_t)Bd*Sd*Dd)

__device__ float g_qkv[(size_t)Md*3072];
__device__ float g_wv[Md*Dd];
__device__ float g_h[Md*192];
__device__ float g_hpart[4*(size_t)Md*192];
__device__ float g_Bt3f[3072*192];
__device__ float g_Bt[Dd*64];
__device__ float g_gpart[8*3072];
__device__ float g_xwpart[8*Bd*3072];
__device__ float g_scores[Md];
__device__ float g_wsm[Md];
__device__ float g_pooled[Bd*Dd];
__device__ float g_route[Bd*8];

__device__ __forceinline__ float warpRedSum(float v){
    #pragma unroll
    for (int o=16;o;o>>=1) v += __shfl_xor_sync(0xffffffffu, v, o);
    return v;
}
__device__ __forceinline__ float warpRedMax(float v){
    #pragma unroll
    for (int o=16;o;o>>=1) v = fmaxf(v, __shfl_xor_sync(0xffffffffu, v, o));
    return v;
}
__device__ __forceinline__ float fexp(float x){
    float t = x * 1.4426950408889634f;
    t = fmaxf(t, -126.0f);
    float ti = floorf(t);
    float f = t - ti;
    float p = 1.5403530393381608e-4f;
    p = fmaf(p, f, 1.3333558146428443e-3f);
    p = fmaf(p, f, 9.6181291076284770e-3f);
    p = fmaf(p, f, 5.5504108664821580e-2f);
    p = fmaf(p, f, 2.4022650695910070e-1f);
    p = fmaf(p, f, 6.9314718055994530e-1f);
    p = fmaf(p, f, 1.0f);
    return __int_as_float(((int)ti + 127) << 23) * p;
}
__device__ __forceinline__ uint32_t f2tf(float f){
    uint32_t r; asm("cvt.rna.tf32.f32 %0, %1;" : "=r"(r) : "f"(f)); return r;
}
__device__ __forceinline__ void mma8(float* d, const uint32_t* a, const uint32_t* b){
    asm volatile("mma.sync.aligned.m16n8k8.row.col.f32.tf32.tf32.f32 "
        "{%0,%1,%2,%3}, {%4,%5,%6,%7}, {%8,%9}, {%0,%1,%2,%3};"
        : "+f"(d[0]),"+f"(d[1]),"+f"(d[2]),"+f"(d[3])
        : "r"(a[0]),"r"(a[1]),"r"(a[2]),"r"(a[3]), "r"(b[0]),"r"(b[1]));
}
__device__ __forceinline__ uint32_t smem_u32(const void* p){
    uint32_t a; asm("{ .reg .u64 t; cvta.to.shared.u64 t, %1; cvt.u32.u64 %0, t; }" : "=r"(a) : "l"(p));
    return a;
}
__device__ __forceinline__ void cpa16(uint32_t dst, const void* src, int ok){
    asm volatile("cp.async.cg.shared.global [%0], [%1], 16, %2;"
        :: "r"(dst), "l"(src), "r"(ok ? 16 : 0));
}
#define CPA_COMMIT asm volatile("cp.async.commit_group;" ::: "memory")
#define CPA_WAIT(n) asm volatile("cp.async.wait_group %0;" :: "n"(n) : "memory")

// ---- tf32 mma.sync GEMM; tiles converted to tf32 in-place once per chunk ----
#define GSTRIDE 36
#define GEMM_SMEM (4*128*GSTRIDE*4)
__global__ __launch_bounds__(256,2)
void mma_gemm(const float* __restrict__ A,
              const float* __restrict__ B0, const float* __restrict__ B1,
              const float* __restrict__ B2s, int segShift,
              float* __restrict__ C,
              int M, int N, int K, int lda, int ldb, int ldc,
              const float* __restrict__ A2, int lda2,
              const float* __restrict__ BK2, int ldbk2, int K1,
              long long sCz,
              float alpha,
              const float* __restrict__ bias0, const float* __restrict__ bias1,
              const float* __restrict__ bias2,
              const float* __restrict__ route, int addC)
{
    extern __shared__ __align__(16) float sm[];
    float* As = sm;
    float* Bs = sm + 2*128*GSTRIDE;

    const int tid = threadIdx.x, wid = tid >> 5, lane = tid & 31;
    const int wm = wid >> 2, wn = wid & 3;
    const int lr = lane >> 2, lc = lane & 3;
    const int bm = blockIdx.y*128, bn = blockIdx.x*128;
    const int zc = blockIdx.z;
    const int kzbase = zc * K;
    C += (size_t)zc * sCz;

    const int row = tid >> 3, c4 = (tid & 7) << 2;
    const float* Ab  = A  + (size_t)bm*lda;
    const float* A2b = A2 + (size_t)bm*lda2;
    const int nch = K >> 5;
    const int segMask = (segShift >= 0) ? ((1 << segShift) - 1) : -1;
    const uint32_t sA = smem_u32(As), sB = smem_u32(Bs);

    auto issue = [&](int c){
        int buf = c & 1;
        int kglob = kzbase + (c << 5);
        bool sec = (kglob >= K1);
        const float* Asrc = sec ? A2b : Ab;
        int la = sec ? lda2 : lda;
        int kk = (sec ? (kglob - K1) : kglob) + c4;
        #pragma unroll
        for (int j=0;j<4;j++){
            int rr = row + j*32;
            int n = bn + rr;
            int bok = n < N;
            cpa16(sA + (uint32_t)((buf*128 + rr)*GSTRIDE + c4)*4,
                  Asrc + (size_t)rr*la + kk, 1);
            const float* Bsrc;
            if (sec){
                Bsrc = BK2 + (size_t)(bok ? n : 0)*ldbk2;
            } else if (segShift >= 0){
                int sel = bok ? (n >> segShift) : 0;
                int rowb = bok ? (n & segMask) : 0;
                const float* Bp = (sel==0) ? B0 : (sel==1 ? B1 : B2s);
                Bsrc = Bp + (size_t)rowb*ldb;
            } else {
                Bsrc = B0 + (size_t)(bok ? n : 0)*ldb;
            }
            cpa16(sB + (uint32_t)((buf*128 + rr)*GSTRIDE + c4)*4, Bsrc + kk, bok);
        }
        CPA_COMMIT;
    };
    // in-place tf32 conversion of one chunk's A+B tiles (each thread: 32 values)
    auto convbuf = [&](int buf){
        int rowc = tid >> 1;
        int c16 = (tid & 1) << 4;
        float* Ap = As + (buf*128 + rowc)*GSTRIDE + c16;
        float* Bp = Bs + (buf*128 + rowc)*GSTRIDE + c16;
        #pragma unroll
        for (int j=0;j<4;j++){
            float4 va = *(float4*)(Ap + j*4);
            uint4 ua; ua.x=f2tf(va.x); ua.y=f2tf(va.y); ua.z=f2tf(va.z); ua.w=f2tf(va.w);
            *(uint4*)(Ap + j*4) = ua;
            float4 vb = *(float4*)(Bp + j*4);
            uint4 ub; ub.x=f2tf(vb.x); ub.y=f2tf(vb.y); ub.z=f2tf(vb.z); ub.w=f2tf(vb.w);
            *(uint4*)(Bp + j*4) = ub;
        }
    };

    float acc[4][4][4];
    #pragma unroll
    for (int i=0;i<4;i++)
        #pragma unroll
        for (int j=0;j<4;j++)
            #pragma unroll
            for (int r=0;r<4;r++) acc[i][j][r]=0.f;

    issue(0);
    if (nch > 1){ issue(1); CPA_WAIT(1); } else CPA_WAIT(0);
    __syncthreads();
    convbuf(0);
    __syncthreads();

    for (int c = 0; c < nch; c++){
        const uint32_t* Ac = (const uint32_t*)As + (c&1)*128*GSTRIDE;
        const uint32_t* Bc = (const uint32_t*)Bs + (c&1)*128*GSTRIDE;
        #pragma unroll
        for (int ks=0; ks<4; ks++){
            uint32_t af[4][4], bf[4][2];
            #pragma unroll
            for (int mt=0; mt<4; mt++){
                const uint32_t* p = Ac + (wm*64 + mt*16)*GSTRIDE + ks*8;
                af[mt][0] = p[lr*GSTRIDE + lc];
                af[mt][1] = p[(lr+8)*GSTRIDE + lc];
                af[mt][2] = p[lr*GSTRIDE + lc + 4];
                af[mt][3] = p[(lr+8)*GSTRIDE + lc + 4];
            }
            #pragma unroll
            for (int nt=0; nt<4; nt++){
                const uint32_t* p = Bc + (wn*32 + nt*8)*GSTRIDE + ks*8;
                bf[nt][0] = p[lr*GSTRIDE + lc];
                bf[nt][1] = p[lr*GSTRIDE + lc + 4];
            }
            #pragma unroll
            for (int mt=0; mt<4; mt++)
                #pragma unroll
                for (int nt=0; nt<4; nt++)
                    mma8(acc[mt][nt], af[mt], bf[nt]);
        }
        __syncthreads();
        if (c+2 < nch) issue(c+2);
        if (c+1 < nch){
            if (c+2 < nch) CPA_WAIT(1); else CPA_WAIT(0);
            __syncthreads();
            convbuf((c+1)&1);
            __syncthreads();
        }
    }

    #pragma unroll
    for (int mt=0; mt<4; mt++){
        #pragma unroll
        for (int nt=0; nt<4; nt++){
            int n = bn + wn*32 + nt*8 + 2*lc;
            if (n >= N) continue;
            int m0 = bm + wm*64 + mt*16 + lr;
            float bv0 = 0.f, bv1 = 0.f;
            if (bias0){
                if (segShift >= 0){
                    int sel = n >> segShift;
                    const float* bp = (sel==0) ? bias0 : (sel==1 ? bias1 : bias2);
                    if (bp){ bv0 = bp[n & segMask]; bv1 = bp[(n+1) & segMask]; }
                } else { bv0 = bias0[n]; bv1 = bias0[n+1]; }
            }
            #pragma unroll
            for (int half=0; half<2; half++){
                int m = m0 + half*8;
                float v0 = alpha*acc[mt][nt][half*2+0];
                float v1 = alpha*acc[mt][nt][half*2+1];
                if (route){
                    float rs = route[((m >> 10) << 3) + ((n & 63) >> 3)];
                    v0 *= rs; v1 *= rs;
                }
                v0 += bv0; v1 += bv1;
                float2* cp = (float2*)(C + (size_t)m*ldc + n);
                if (addC){ float2 o = *cp; v0 += o.x; v1 += o.y; }
                *cp = make_float2(v0, v1);
            }
        }
    }
}

// reduce split-K partials + apply route
__global__ void red_h(const float* __restrict__ hp, const float* __restrict__ route,
                      float* __restrict__ h, int C){
    int idx = blockIdx.x*256 + threadIdx.x;
    if (idx >= Md*C) return;
    int m = idx / C, c = idx - m*C;
    size_t stride = (size_t)Md*C;
    float s = hp[idx] + hp[stride + idx] + hp[2*stride + idx] + hp[3*stride + idx];
    h[(size_t)m*192 + c] = s * route[((m >> 10) << 3) + ((c & 63) >> 3)];
}

// ---- fused flash attention (unchanged) ----
#define AQS 36
#define AVS 72
#define ATTN_SMEM ((2*128*AQS + 2*128*AQS + 4*32*AVS)*4)
__global__ __launch_bounds__(256,2) void attn_fused(
    const float* __restrict__ qkv, float* __restrict__ qk, float* __restrict__ wv)
{
    extern __shared__ __align__(16) float dsm[];
    float* Qs = dsm;
    float* Ks = dsm + 2*128*AQS;
    float* Vs = Ks + 2*128*AQS;

    const int z = blockIdx.y;
    const int bq = z >> 4, h = z & 15;
    const int bm = blockIdx.x * 128;
    const float* Qg = qkv + (size_t)bq*Sd*3072 + h*64;
    const float* Kg = Qg + 1024;
    const float* Vg = Qg + 2048;
    float* qko = qk + (size_t)z*Sd*Sd;

    const int tid = threadIdx.x, wid = tid >> 5, lane = tid & 31;
    const int lr = lane >> 2, lc = lane & 3;
    const int wr = wid * 16;
    const int rr0 = tid >> 3, c4 = (tid & 7) << 2;
    const uint32_t sQ = smem_u32(Qs), sK = smem_u32(Ks), sV = smem_u32(Vs);

    auto issueK = [&](int ct){
        int kb = ct << 7;
        #pragma unroll
        for (int j=0;j<4;j++){
            int rr = rr0 + j*32;
            #pragma unroll
            for (int ch=0;ch<2;ch++)
                cpa16(sK + (uint32_t)(((ch*128 + rr)*AQS + c4)*4),
                      Kg + (size_t)(kb+rr)*3072 + ch*32 + c4, 1);
        }
        CPA_COMMIT;
    };
    auto issueV = [&](int ct){
        int kb = ct << 7;
        #pragma unroll
        for (int j=0;j<8;j++){
            int idx = tid + (j << 8);
            int vk = idx >> 4, vc4 = (idx & 15) << 2;
            int w8 = vk & 7;
            int slot = (vk & ~7) | (w8 >> 1) | ((w8 & 1) << 2);
            cpa16(sV + (uint32_t)((((slot>>5)*32 + (slot&31))*AVS + vc4)*4),
                  Vg + (size_t)(kb+vk)*3072 + vc4, 1);
        }
        CPA_COMMIT;
    };
    auto convQK = [&](float* base, float scale){
        #pragma unroll
        for (int j=0;j<4;j++){
            int rr = rr0 + j*32;
            #pragma unroll
            for (int ch=0;ch<2;ch++){
                float4* p = (float4*)(base + (ch*128 + rr)*AQS + c4);
                float4 v = *p;
                uint4 u;
                u.x = f2tf(v.x*scale); u.y = f2tf(v.y*scale);
                u.z = f2tf(v.z*scale); u.w = f2tf(v.w*scale);
                *(uint4*)p = u;
            }
        }
    };
    auto convV = [&](){
        #pragma unroll
        for (int j=0;j<8;j++){
            int idx = tid + (j << 8);
            int vk = idx >> 4, vc4 = (idx & 15) << 2;
            float4* p = (float4*)(Vs + (vk>>5)*32*AVS + (vk&31)*AVS + vc4);
            float4 v = *p;
            uint4 u;
            u.x = f2tf(v.x); u.y = f2tf(v.y); u.z = f2tf(v.z); u.w = f2tf(v.w);
            *(uint4*)p = u;
        }
    };

    #pragma unroll
    for (int j=0;j<4;j++){
        int rr = rr0 + j*32;
        #pragma unroll
        for (int ch=0;ch<2;ch++)
            cpa16(sQ + (uint32_t)(((ch*128 + rr)*AQS + c4)*4),
                  Qg + (size_t)(bm+rr)*3072 + ch*32 + c4, 1);
    }
    CPA_COMMIT;
    issueK(0); issueV(0);
    CPA_WAIT(1);
    __syncthreads();
    convQK(Qs, 0.125f);
    convQK(Ks, 1.f);
    __syncthreads();

    float runmax[2] = {-1e30f,-1e30f}, runsum[2] = {0.f,0.f};
    float pvacc[8][4];
    #pragma unroll
    for (int i=0;i<8;i++)
        #pragma unroll
        for (int r=0;r<4;r++) pvacc[i][r]=0.f;

    const int m0 = bm + wr + lr;

    for (int ct=0; ct<8; ct++){
        const int kb = ct*128;

        float sacc[16][4];
        #pragma unroll
        for (int i=0;i<16;i++)
            #pragma unroll
            for (int r=0;r<4;r++) sacc[i][r]=0.f;
        #pragma unroll
        for (int ch=0;ch<2;ch++){
            const uint32_t* Qc = (const uint32_t*)Qs + ch*128*AQS;
            const uint32_t* Kc = (const uint32_t*)Ks + ch*128*AQS;
            #pragma unroll
            for (int ks=0;ks<4;ks++){
                uint32_t af[4];
                const uint32_t* p = Qc + (wr+lr)*AQS + ks*8;
                af[0] = p[lc];
                af[1] = p[8*AQS + lc];
                af[2] = p[lc + 4];
                af[3] = p[8*AQS + lc + 4];
                #pragma unroll
                for (int nt=0;nt<16;nt++){
                    const uint32_t* q = Kc + (nt*8+lr)*AQS + ks*8;
                    uint32_t bf[2];
                    bf[0] = q[lc];
                    bf[1] = q[lc + 4];
                    mma8(sacc[nt], af, bf);
                }
            }
        }
        __syncthreads();
        if (ct < 7) issueK(ct+1);

        #pragma unroll
        for (int nt=0;nt<16;nt++){
            int n = kb + nt*8 + 2*lc;
            __stcs((float2*)(qko + (size_t)m0*Sd + n),     make_float2(sacc[nt][0], sacc[nt][1]));
            __stcs((float2*)(qko + (size_t)(m0+8)*Sd + n), make_float2(sacc[nt][2], sacc[nt][3]));
        }
        #pragma unroll
        for (int half=0;half<2;half++){
            float tm = -1e30f;
            #pragma unroll
            for (int nt=0;nt<16;nt++)
                tm = fmaxf(tm, fmaxf(sacc[nt][half*2], sacc[nt][half*2+1]));
            tm = fmaxf(tm, __shfl_xor_sync(0xffffffffu, tm, 1));
            tm = fmaxf(tm, __shfl_xor_sync(0xffffffffu, tm, 2));
            float mn = fmaxf(runmax[half], tm);
            float f = fexp(runmax[half] - mn);
            runmax[half] = mn;
            runsum[half] *= f;
            #pragma unroll
            for (int nt=0;nt<8;nt++){
                pvacc[nt][half*2+0] *= f;
                pvacc[nt][half*2+1] *= f;
            }
            float s = 0.f;
            #pragma unroll
            for (int nt=0;nt<16;nt++){
                float p0 = fexp(sacc[nt][half*2+0] - mn);
                float p1 = fexp(sacc[nt][half*2+1] - mn);
                s += p0 + p1;
                sacc[nt][half*2+0] = p0;
                sacc[nt][half*2+1] = p1;
            }
            s += __shfl_xor_sync(0xffffffffu, s, 1);
            s += __shfl_xor_sync(0xffffffffu, s, 2);
            runsum[half] += s;
        }
        if (ct < 7) CPA_WAIT(1); else CPA_WAIT(0);
        __syncthreads();
        convV();
        __syncthreads();

        #pragma unroll
        for (int ks=0;ks<16;ks++){
            uint32_t af[4];
            af[0] = f2tf(sacc[ks][0]);
            af[1] = f2tf(sacc[ks][2]);
            af[2] = f2tf(sacc[ks][1]);
            af[3] = f2tf(sacc[ks][3]);
            const uint32_t* pbase = (const uint32_t*)Vs + (ks>>2)*32*AVS + ((ks&3)*8)*AVS;
            #pragma unroll
            for (int nt=0;nt<8;nt++){
                const uint32_t* p = pbase + nt*8;
                uint32_t bf[2];
                bf[0] = p[lc*AVS + lr];
                bf[1] = p[(lc+4)*AVS + lr];
                mma8(pvacc[nt], af, bf);
            }
        }
        __syncthreads();
        if (ct < 7){
            issueV(ct+1);
            CPA_WAIT(1);
            __syncthreads();
            convQK(Ks, 1.f);
            __syncthreads();
        }
    }

    float* Cw = wv + (size_t)bq*Sd*Dd + h*DHd;
    float inv0 = 1.f / runsum[0], inv1 = 1.f / runsum[1];
    #pragma unroll
    for (int nt=0;nt<8;nt++){
        int n = nt*8 + 2*lc;
        *(float2*)(Cw + (size_t)m0*Dd + n)     = make_float2(pvacc[nt][0]*inv0, pvacc[nt][1]*inv0);
        *(float2*)(Cw + (size_t)(m0+8)*Dd + n) = make_float2(pvacc[nt][2]*inv1, pvacc[nt][3]*inv1);
    }
}

// ---- router ----
__global__ __launch_bounds__(256) void r_g(const float* __restrict__ cw,
                                           const float* __restrict__ pw, float* __restrict__ gpart){
    int idx = blockIdx.x*256 + threadIdx.x;
    int oz = blockIdx.y;
    const float* base = cw + (size_t)(oz*128)*3072 + idx;
    const float* pwb = pw + oz*128;
    float a0=0.f, a1=0.f;
    #pragma unroll 8
    for (int o=0;o<128;o+=2){
        a0 = fmaf(pwb[o],   base[(size_t)o*3072], a0);
        a1 = fmaf(pwb[o+1], base[(size_t)(o+1)*3072], a1);
    }
    gpart[oz*3072 + idx] = a0 + a1;
}
__global__ __launch_bounds__(256) void r_scores8(const float* __restrict__ x,
                                                 const float* __restrict__ gpart, float* __restrict__ scores){
    int m0 = blockIdx.x*8;
    int tid = threadIdx.x;
    __shared__ float gs[3072];
    __shared__ float sm[8];
    #pragma unroll
    for (int j=0;j<12;j++){
        int i = tid + j*256;
        float t = 0.f;
        #pragma unroll
        for (int oz=0;oz<8;oz++) t += gpart[oz*3072 + i];
        gs[i] = t;
    }
    __syncthreads();
    for (int r=0;r<8;r++){
        int m = m0 + r;
        int s = m & 1023;
        const float* x0 = x + (size_t)m*Dd;
        bool okm = (s > 0), okp = (s < 1023);
        float acc = 0.f;
        #pragma unroll
        for (int j=0;j<4;j++){
            int i = tid + j*256;
            float vm = okm ? x0[i - Dd] : 0.f;
            float v0 = x0[i];
            float vp = okp ? x0[i + Dd] : 0.f;
            const float* gg = gs + i*3;
            acc = fmaf(gg[0], vm, acc);
            acc = fmaf(gg[1], v0, acc);
            acc = fmaf(gg[2], vp, acc);
        }
        acc = warpRedSum(acc);
        if ((tid&31)==0) sm[tid>>5]=acc;
        __syncthreads();
        if (tid==0){
            float t = 0.f;
            #pragma unroll
            for (int i=0;i<8;i++) t += sm[i];
            scores[m] = t;
        }
        __syncthreads();
    }
}
__global__ void softmax_w(const float* __restrict__ scores, float* __restrict__ w){
    int b = blockIdx.x, tid = threadIdx.x;
    float4 v = *(const float4*)(scores + (size_t)b*Sd + tid*4);
    float m = fmaxf(fmaxf(v.x,v.y), fmaxf(v.z,v.w));
    m = warpRedMax(m);
    __shared__ float sm[8];
    __shared__ float gmax, gisum;
    if ((tid&31)==0) sm[tid>>5]=m;
    __syncthreads();
    if (tid==0){ float mm=sm[0]; for(int i=1;i<8;i++) mm=fmaxf(mm,sm[i]); gmax=mm; }
    __syncthreads();
    float e0=expf(v.x-gmax), e1=expf(v.y-gmax), e2=expf(v.z-gmax), e3=expf(v.w-gmax);
    float s = e0+e1+e2+e3;
    s = warpRedSum(s);
    if ((tid&31)==0) sm[tid>>5]=s;
    __syncthreads();
    if (tid==0){ float ss=0; for(int i=0;i<8;i++) ss+=sm[i]; gisum = 1.f/ss; }
    __syncthreads();
    *(float4*)(w + (size_t)b*Sd + tid*4) = make_float4(e0*gisum, e1*gisum, e2*gisum, e3*gisum);
}
__global__ __launch_bounds__(128) void r_xw(const float* __restrict__ x,
                                            const float* __restrict__ w, float* __restrict__ xwpart){
    int b = blockIdx.y;
    int sc = blockIdx.z;
    int i = blockIdx.x*128 + threadIdx.x;
    int s0 = sc*128;
    __shared__ float ws[130];
    for (int j = threadIdx.x; j < 130; j += 128){
        int s = s0 - 1 + j;
        ws[j] = ((unsigned)s < 1024u) ? w[(size_t)b*Sd + s] : 0.f;
    }
    __syncthreads();
    const float* xb = x + ((size_t)b*Sd + s0)*Dd + i;
    float a0=0.f, a1=0.f, a2=0.f;
    #pragma unroll 8
    for (int j=0;j<128;j++){
        float v = xb[(size_t)j*Dd];
        a0 = fmaf(ws[j+2], v, a0);
        a1 = fmaf(ws[j+1], v, a1);
        a2 = fmaf(ws[j],   v, a2);
    }
    float* o = xwpart + ((size_t)(sc*Bd + b))*3072 + i*3;
    o[0]=a0; o[1]=a1; o[2]=a2;
}
__global__ __launch_bounds__(256) void r_pooled(const float* __restrict__ cw,
                                                const float* __restrict__ cb,
                                                const float* __restrict__ xwpart, float* __restrict__ pooled){
    int b = blockIdx.y;
    int d = blockIdx.x*8 + (threadIdx.x >> 5);
    int lane = threadIdx.x & 31;
    __shared__ float sx[3072];
    for (int j = threadIdx.x; j < 3072; j += 256){
        float t = 0.f;
        #pragma unroll
        for (int sc=0;sc<8;sc++) t += xwpart[((size_t)(sc*Bd + b))*3072 + j];
        sx[j] = t;
    }
    __syncthreads();
    const float4* cr = (const float4*)(cw + (size_t)d*3072);
    float acc = 0.f;
    #pragma unroll
    for (int j=0;j<24;j++){
        float4 c = cr[lane + j*32];
        const float* s = sx + (lane + j*32)*4;
        acc += c.x*s[0] + c.y*s[1] + c.z*s[2] + c.w*s[3];
    }
    acc = warpRedSum(acc);
    if (lane == 0) pooled[b*Dd + d] = acc + cb[d];
}
__global__ void route_k(const float* __restrict__ pooled, const float* __restrict__ rw,
                        const float* __restrict__ rb, float* __restrict__ route){
    int b = blockIdx.x;
    int tid = threadIdx.x;
    int e = tid >> 5, lane = tid & 31;
    __shared__ float lg[8];
    float s=0.f;
    for (int d=lane; d<Dd; d+=32) s += pooled[b*Dd+d]*rw[e*Dd+d];
    s = warpRedSum(s);
    if (lane==0) lg[e] = s + rb[e];
    __syncthreads();
    if (tid==0){
        float mm=lg[0];
        for (int i=1;i<8;i++) mm=fmaxf(mm,lg[i]);
        float ex[8]; float ss=0.f;
        for (int i=0;i<8;i++){ ex[i]=expf(lg[i]-mm); ss+=ex[i]; }
        float inv = 1.f/ss;
        for (int i=0;i<8;i++) route[b*8+i]=ex[i]*inv;
    }
}

// ---- prep ----
__global__ void build_Bt3f(const float* __restrict__ B0, const float* __restrict__ B1,
                           const float* __restrict__ B2, float* __restrict__ Bt){
    int idx = blockIdx.x*blockDim.x + threadIdx.x;
    if (idx >= 3072*192) return;
    int n = idx / 192, c = idx - n*192;
    int p = n >> 10, pp = c >> 6;
    float val = 0.f;
    if (pp == p){
        int e = (c >> 3) & 7, r = c & 7;
        const float* Bp = (p==0) ? B0 : (p==1 ? B1 : B2);
        val = 2.f * Bp[(size_t)e*Dd*8 + (size_t)(n & 1023)*8 + r];
    }
    Bt[idx] = val;
}
__global__ void tr_loraB2x(const float* __restrict__ Bp, float* __restrict__ Bt){
    int idx = blockIdx.x*blockDim.x + threadIdx.x;
    if (idx >= Dd*64) return;
    int n = idx >> 6, e = (idx >> 3) & 7, r = idx & 7;
    Bt[idx] = 2.f * Bp[(size_t)e*Dd*8 + (size_t)n*8 + r];
}

// ---- host launcher (stream-forked) ----
extern "C" void kernel_launch(void* const* d_in, const int* in_sizes, int n_in,
                              void* d_out, int out_size)
{
    (void)in_sizes; (void)n_in; (void)out_size;
    const float* x      = (const float*)d_in[0];
    const float* conv_w = (const float*)d_in[1];
    const float* conv_b = (const float*)d_in[2];
    const float* pool_w = (const float*)d_in[3];
    const float* pool_b = (const float*)d_in[4];
    const float* rlin_w = (const float*)d_in[5];
    const float* rlin_b = (const float*)d_in[6];
    const float* qW=(const float*)d_in[7],  *qb=(const float*)d_in[8];
    const float* qA=(const float*)d_in[9],  *qB=(const float*)d_in[10];
    const float* kW=(const float*)d_in[11], *kA=(const float*)d_in[12], *kB=(const float*)d_in[13];
    const float* vW=(const float*)d_in[14], *vb=(const float*)d_in[15];
    const float* vA=(const float*)d_in[16], *vB=(const float*)d_in[17];
    const float* oW=(const float*)d_in[18], *ob=(const float*)d_in[19];
    const float* oA=(const float*)d_in[20], *oB=(const float*)d_in[21];
    (void)pool_b;

    float* out = (float*)d_out;
    float* qk  = out + OUT_OFF;

    float *qkv,*wv,*h,*hpart,*Bt3f,*Bt,*gpart,*xwpart,*scores,*w,*pooled,*route;
    cudaGetSymbolAddress((void**)&qkv, g_qkv);
    cudaGetSymbolAddress((void**)&wv, g_wv);
    cudaGetSymbolAddress((void**)&h,  g_h);
    cudaGetSymbolAddress((void**)&hpart, g_hpart);
    cudaGetSymbolAddress((void**)&Bt3f, g_Bt3f);
    cudaGetSymbolAddress((void**)&Bt,  g_Bt);
    cudaGetSymbolAddress((void**)&gpart, g_gpart);
    cudaGetSymbolAddress((void**)&xwpart, g_xwpart);
    cudaGetSymbolAddress((void**)&scores, g_scores);
    cudaGetSymbolAddress((void**)&w,  g_wsm);
    cudaGetSymbolAddress((void**)&pooled, g_pooled);
    cudaGetSymbolAddress((void**)&route,  g_route);

    cudaFuncSetAttribute(mma_gemm, cudaFuncAttributeMaxDynamicSharedMemorySize, GEMM_SMEM);
    cudaFuncSetAttribute(attn_fused, cudaFuncAttributeMaxDynamicSharedMemorySize, ATTN_SMEM);

    cudaStream_t s2;
    cudaEvent_t ev1, ev2, ev3, ev4;
    cudaStreamCreateWithFlags(&s2, cudaStreamNonBlocking);
    cudaEventCreateWithFlags(&ev1, cudaEventDisableTiming);
    cudaEventCreateWithFlags(&ev2, cudaEventDisableTiming);
    cudaEventCreateWithFlags(&ev3, cudaEventDisableTiming);
    cudaEventCreateWithFlags(&ev4, cudaEventDisableTiming);

    cudaEventRecord(ev1, 0);
    cudaStreamWaitEvent(s2, ev1, 0);

    build_Bt3f<<<(3072*192 + 255)/256, 256, 0, s2>>>(qB, kB, vB, Bt3f);
    tr_loraB2x<<<(Dd*64 + 255)/256, 256, 0, s2>>>(oB, Bt);
    mma_gemm<<<dim3(2,32,4), 256, GEMM_SMEM, s2>>>(x, qA, kA, vA, 6, hpart,
        Md, 192, 256, 1024, 1024, 192,
        x, 1024, x, 1024, 1<<30,
        (long long)Md*192,
        1.f, nullptr, nullptr, nullptr, nullptr, 0);
    mma_gemm<<<dim3(24,32,1), 256, GEMM_SMEM, s2>>>(x, qW, kW, vW, 10, qkv,
        Md, 3072, 1024, 1024, 1024, 3072,
        x, 1024, x, 1024, 1<<30,
        0,
        1.f, qb, nullptr, vb, nullptr, 0);

    r_g<<<dim3(12,8), 256>>>(conv_w, pool_w, gpart);
    r_scores8<<<Md/8, 256>>>(x, gpart, scores);
    softmax_w<<<Bd, 256>>>(scores, w);
    r_xw<<<dim3(8,Bd,8), 128>>>(x, w, xwpart);
    r_pooled<<<dim3(128,Bd), 256>>>(conv_w, conv_b, xwpart, pooled);
    route_k<<<Bd, 256>>>(pooled, rlin_w, rlin_b, route);

    cudaEventRecord(ev2, s2);
    cudaStreamWaitEvent(0, ev2, 0);

    red_h<<<(Md*192 + 255)/256, 256>>>(hpart, route, h, 192);
    mma_gemm<<<dim3(24,32,1), 256, GEMM_SMEM>>>(h, Bt3f, Bt3f, Bt3f, -1, qkv,
        Md, 3072, 192, 192, 192, 3072,
        h, 192, h, 192, 1<<30,
        0,
        1.f, nullptr, nullptr, nullptr, nullptr, 1);

    attn_fused<<<dim3(8,64), 256, ATTN_SMEM>>>(qkv, qk, wv);

    cudaEventRecord(ev3, 0);
    cudaStreamWaitEvent(s2, ev3, 0);
    mma_gemm<<<dim3(1,32,4), 256, GEMM_SMEM, s2>>>(wv, oA, oA, oA, -1, hpart,
        Md, 64, 256, 1024, 1024, 64,
        wv, 1024, wv, 1024, 1<<30,
        (long long)Md*64,
        1.f, nullptr, nullptr, nullptr, nullptr, 0);
    red_h<<<(Md*64 + 255)/256, 256, 0, s2>>>(hpart, route, h, 64);

    mma_gemm<<<dim3(8,32,1), 256, GEMM_SMEM>>>(wv, oW, oW, oW, -1, out,
        Md, 1024, 1024, 1024, 1024, 1024,
        wv, 1024, wv, 1024, 1<<30,
        0,
        1.f, ob, nullptr, nullptr, nullptr, 0);

    cudaEventRecord(ev4, s2);
    cudaStreamWaitEvent(0, ev4, 0);

    mma_gemm<<<dim3(8,32,1), 256, GEMM_SMEM>>>(h, Bt, Bt, Bt, -1, out,
        Md, 1024, 64, 192, 64, 1024,
        h, 192, h, 192, 1<<30,
        0,
        1.f, nullptr, nullptr, nullptr, nullptr, 1);
}

// round 16
// speedup vs baseline: 1.0519x; 1.0519x over previous
#include <cuda_runtime.h>
#include <cstdint>
#include <cstddef>

#define Bd 4
#define Sd 1024
#define Dd 1024
#define Hd 16
#define DHd 64
#define Md (Bd*Sd)
#define OUT_OFF ((size_t)Bd*Sd*Dd)

__device__ float g_qkv[(size_t)Md*3072];
__device__ float g_wv[Md*Dd];
__device__ float g_h[Md*192];
__device__ float g_hpart[4*(size_t)Md*192];
__device__ float g_Bt3f[3072*192];
__device__ float g_Bt[Dd*64];
__device__ float g_gpart[8*3072];
__device__ float g_xwpart[8*Bd*3072];
__device__ float g_scores[Md];
__device__ float g_wsm[Md];
__device__ float g_pooled[Bd*Dd];
__device__ float g_route[Bd*8];

__device__ __forceinline__ float warpRedSum(float v){
    #pragma unroll
    for (int o=16;o;o>>=1) v += __shfl_xor_sync(0xffffffffu, v, o);
    return v;
}
__device__ __forceinline__ float warpRedMax(float v){
    #pragma unroll
    for (int o=16;o;o>>=1) v = fmaxf(v, __shfl_xor_sync(0xffffffffu, v, o));
    return v;
}
__device__ __forceinline__ float fexp(float x){
    float t = x * 1.4426950408889634f;
    t = fmaxf(t, -126.0f);
    float ti = floorf(t);
    float f = t - ti;
    float p = 1.5403530393381608e-4f;
    p = fmaf(p, f, 1.3333558146428443e-3f);
    p = fmaf(p, f, 9.6181291076284770e-3f);
    p = fmaf(p, f, 5.5504108664821580e-2f);
    p = fmaf(p, f, 2.4022650695910070e-1f);
    p = fmaf(p, f, 6.9314718055994530e-1f);
    p = fmaf(p, f, 1.0f);
    return __int_as_float(((int)ti + 127) << 23) * p;
}
__device__ __forceinline__ uint32_t f2tf(float f){
    uint32_t r; asm("cvt.rna.tf32.f32 %0, %1;" : "=r"(r) : "f"(f)); return r;
}
__device__ __forceinline__ void mma8(float* d, const uint32_t* a, const uint32_t* b){
    asm volatile("mma.sync.aligned.m16n8k8.row.col.f32.tf32.tf32.f32 "
        "{%0,%1,%2,%3}, {%4,%5,%6,%7}, {%8,%9}, {%0,%1,%2,%3};"
        : "+f"(d[0]),"+f"(d[1]),"+f"(d[2]),"+f"(d[3])
        : "r"(a[0]),"r"(a[1]),"r"(a[2]),"r"(a[3]), "r"(b[0]),"r"(b[1]));
}
__device__ __forceinline__ uint32_t smem_u32(const void* p){
    uint32_t a; asm("{ .reg .u64 t; cvta.to.shared.u64 t, %1; cvt.u32.u64 %0, t; }" : "=r"(a) : "l"(p));
    return a;
}
__device__ __forceinline__ void cpa16(uint32_t dst, const void* src, int ok){
    asm volatile("cp.async.cg.shared.global [%0], [%1], 16, %2;"
        :: "r"(dst), "l"(src), "r"(ok ? 16 : 0));
}
#define CPA_COMMIT asm volatile("cp.async.commit_group;" ::: "memory")
#define CPA_WAIT(n) asm volatile("cp.async.wait_group %0;" :: "n"(n) : "memory")

// ---- tf32 mma.sync GEMM (R13 version: fragment-side cvt) ----
#define GSTRIDE 36
#define GEMM_SMEM (4*128*GSTRIDE*4)
__global__ __launch_bounds__(256,2)
void mma_gemm(const float* __restrict__ A,
              const float* __restrict__ B0, const float* __restrict__ B1,
              const float* __restrict__ B2s, int segShift,
              float* __restrict__ C,
              int M, int N, int K, int lda, int ldb, int ldc,
              const float* __restrict__ A2, int lda2,
              const float* __restrict__ BK2, int ldbk2, int K1,
              long long sCz,
              float alpha,
              const float* __restrict__ bias0, const float* __restrict__ bias1,
              const float* __restrict__ bias2,
              const float* __restrict__ route, int addC)
{
    extern __shared__ __align__(16) float sm[];
    float* As = sm;
    float* Bs = sm + 2*128*GSTRIDE;

    const int tid = threadIdx.x, wid = tid >> 5, lane = tid & 31;
    const int wm = wid >> 2, wn = wid & 3;
    const int lr = lane >> 2, lc = lane & 3;
    const int bm = blockIdx.y*128, bn = blockIdx.x*128;
    const int zc = blockIdx.z;
    const int kzbase = zc * K;
    C += (size_t)zc * sCz;

    const int row = tid >> 3, c4 = (tid & 7) << 2;
    const float* Ab  = A  + (size_t)bm*lda;
    const float* A2b = A2 + (size_t)bm*lda2;
    const int nch = K >> 5;
    const int segMask = (segShift >= 0) ? ((1 << segShift) - 1) : -1;
    const uint32_t sA = smem_u32(As), sB = smem_u32(Bs);

    auto issue = [&](int c){
        int buf = c & 1;
        int kglob = kzbase + (c << 5);
        bool sec = (kglob >= K1);
        const float* Asrc = sec ? A2b : Ab;
        int la = sec ? lda2 : lda;
        int kk = (sec ? (kglob - K1) : kglob) + c4;
        #pragma unroll
        for (int j=0;j<4;j++){
            int rr = row + j*32;
            int n = bn + rr;
            int bok = n < N;
            cpa16(sA + (uint32_t)((buf*128 + rr)*GSTRIDE + c4)*4,
                  Asrc + (size_t)rr*la + kk, 1);
            const float* Bsrc;
            if (sec){
                Bsrc = BK2 + (size_t)(bok ? n : 0)*ldbk2;
            } else if (segShift >= 0){
                int sel = bok ? (n >> segShift) : 0;
                int rowb = bok ? (n & segMask) : 0;
                const float* Bp = (sel==0) ? B0 : (sel==1 ? B1 : B2s);
                Bsrc = Bp + (size_t)rowb*ldb;
            } else {
                Bsrc = B0 + (size_t)(bok ? n : 0)*ldb;
            }
            cpa16(sB + (uint32_t)((buf*128 + rr)*GSTRIDE + c4)*4, Bsrc + kk, bok);
        }
        CPA_COMMIT;
    };

    float acc[4][4][4];
    #pragma unroll
    for (int i=0;i<4;i++)
        #pragma unroll
        for (int j=0;j<4;j++)
            #pragma unroll
            for (int r=0;r<4;r++) acc[i][j][r]=0.f;

    issue(0);
    if (nch > 1){ issue(1); CPA_WAIT(1); } else CPA_WAIT(0);
    __syncthreads();

    for (int c = 0; c < nch; c++){
        const float* Ac = As + (c&1)*128*GSTRIDE;
        const float* Bc = Bs + (c&1)*128*GSTRIDE;
        #pragma unroll
        for (int ks=0; ks<4; ks++){
            uint32_t af[4][4], bf[4][2];
            #pragma unroll
            for (int mt=0; mt<4; mt++){
                const float* p = Ac + (wm*64 + mt*16)*GSTRIDE + ks*8;
                af[mt][0] = f2tf(p[lr*GSTRIDE + lc]);
                af[mt][1] = f2tf(p[(lr+8)*GSTRIDE + lc]);
                af[mt][2] = f2tf(p[lr*GSTRIDE + lc + 4]);
                af[mt][3] = f2tf(p[(lr+8)*GSTRIDE + lc + 4]);
            }
            #pragma unroll
            for (int nt=0; nt<4; nt++){
                const float* p = Bc + (wn*32 + nt*8)*GSTRIDE + ks*8;
                bf[nt][0] = f2tf(p[lr*GSTRIDE + lc]);
                bf[nt][1] = f2tf(p[lr*GSTRIDE + lc + 4]);
            }
            #pragma unroll
            for (int mt=0; mt<4; mt++)
                #pragma unroll
                for (int nt=0; nt<4; nt++)
                    mma8(acc[mt][nt], af[mt], bf[nt]);
        }
        __syncthreads();
        if (c+2 < nch) issue(c+2);
        if (c+1 < nch){
            if (c+2 < nch) CPA_WAIT(1); else CPA_WAIT(0);
            __syncthreads();
        }
    }

    #pragma unroll
    for (int mt=0; mt<4; mt++){
        #pragma unroll
        for (int nt=0; nt<4; nt++){
            int n = bn + wn*32 + nt*8 + 2*lc;
            if (n >= N) continue;
            int m0 = bm + wm*64 + mt*16 + lr;
            float bv0 = 0.f, bv1 = 0.f;
            if (bias0){
                if (segShift >= 0){
                    int sel = n >> segShift;
                    const float* bp = (sel==0) ? bias0 : (sel==1 ? bias1 : bias2);
                    if (bp){ bv0 = bp[n & segMask]; bv1 = bp[(n+1) & segMask]; }
                } else { bv0 = bias0[n]; bv1 = bias0[n+1]; }
            }
            #pragma unroll
            for (int half=0; half<2; half++){
                int m = m0 + half*8;
                float v0 = alpha*acc[mt][nt][half*2+0];
                float v1 = alpha*acc[mt][nt][half*2+1];
                if (route){
                    float rs = route[((m >> 10) << 3) + ((n & 63) >> 3)];
                    v0 *= rs; v1 *= rs;
                }
                v0 += bv0; v1 += bv1;
                float2* cp = (float2*)(C + (size_t)m*ldc + n);
                if (addC){ float2 o = *cp; v0 += o.x; v1 += o.y; }
                *cp = make_float2(v0, v1);
            }
        }
    }
}

// reduce split-K partials + apply route (Mrows/bOff for batch-split halves)
__global__ void red_h(const float* __restrict__ hp, const float* __restrict__ route,
                      float* __restrict__ h, int C, int Mrows, int bOff){
    int idx = blockIdx.x*256 + threadIdx.x;
    if (idx >= Mrows*C) return;
    int m = idx / C, c = idx - m*C;
    size_t stride = (size_t)Mrows*C;
    float s = hp[idx] + hp[stride + idx] + hp[2*stride + idx] + hp[3*stride + idx];
    h[(size_t)m*192 + c] = s * route[(((m >> 10) + bOff) << 3) + ((c & 63) >> 3)];
}

// ---- fused flash attention (unchanged) ----
#define AQS 36
#define AVS 72
#define ATTN_SMEM ((2*128*AQS + 2*128*AQS + 4*32*AVS)*4)
__global__ __launch_bounds__(256,2) void attn_fused(
    const float* __restrict__ qkv, float* __restrict__ qk, float* __restrict__ wv)
{
    extern __shared__ __align__(16) float dsm[];
    float* Qs = dsm;
    float* Ks = dsm + 2*128*AQS;
    float* Vs = Ks + 2*128*AQS;

    const int z = blockIdx.y;
    const int bq = z >> 4, h = z & 15;
    const int bm = blockIdx.x * 128;
    const float* Qg = qkv + (size_t)bq*Sd*3072 + h*64;
    const float* Kg = Qg + 1024;
    const float* Vg = Qg + 2048;
    float* qko = qk + (size_t)z*Sd*Sd;

    const int tid = threadIdx.x, wid = tid >> 5, lane = tid & 31;
    const int lr = lane >> 2, lc = lane & 3;
    const int wr = wid * 16;
    const int rr0 = tid >> 3, c4 = (tid & 7) << 2;
    const uint32_t sQ = smem_u32(Qs), sK = smem_u32(Ks), sV = smem_u32(Vs);

    auto issueK = [&](int ct){
        int kb = ct << 7;
        #pragma unroll
        for (int j=0;j<4;j++){
            int rr = rr0 + j*32;
            #pragma unroll
            for (int ch=0;ch<2;ch++)
                cpa16(sK + (uint32_t)(((ch*128 + rr)*AQS + c4)*4),
                      Kg + (size_t)(kb+rr)*3072 + ch*32 + c4, 1);
        }
        CPA_COMMIT;
    };
    auto issueV = [&](int ct){
        int kb = ct << 7;
        #pragma unroll
        for (int j=0;j<8;j++){
            int idx = tid + (j << 8);
            int vk = idx >> 4, vc4 = (idx & 15) << 2;
            int w8 = vk & 7;
            int slot = (vk & ~7) | (w8 >> 1) | ((w8 & 1) << 2);
            cpa16(sV + (uint32_t)((((slot>>5)*32 + (slot&31))*AVS + vc4)*4),
                  Vg + (size_t)(kb+vk)*3072 + vc4, 1);
        }
        CPA_COMMIT;
    };
    auto convQK = [&](float* base, float scale){
        #pragma unroll
        for (int j=0;j<4;j++){
            int rr = rr0 + j*32;
            #pragma unroll
            for (int ch=0;ch<2;ch++){
                float4* p = (float4*)(base + (ch*128 + rr)*AQS + c4);
                float4 v = *p;
                uint4 u;
                u.x = f2tf(v.x*scale); u.y = f2tf(v.y*scale);
                u.z = f2tf(v.z*scale); u.w = f2tf(v.w*scale);
                *(uint4*)p = u;
            }
        }
    };
    auto convV = [&](){
        #pragma unroll
        for (int j=0;j<8;j++){
            int idx = tid + (j << 8);
            int vk = idx >> 4, vc4 = (idx & 15) << 2;
            float4* p = (float4*)(Vs + (vk>>5)*32*AVS + (vk&31)*AVS + vc4);
            float4 v = *p;
            uint4 u;
            u.x = f2tf(v.x); u.y = f2tf(v.y); u.z = f2tf(v.z); u.w = f2tf(v.w);
            *(uint4*)p = u;
        }
    };

    #pragma unroll
    for (int j=0;j<4;j++){
        int rr = rr0 + j*32;
        #pragma unroll
        for (int ch=0;ch<2;ch++)
            cpa16(sQ + (uint32_t)(((ch*128 + rr)*AQS + c4)*4),
                  Qg + (size_t)(bm+rr)*3072 + ch*32 + c4, 1);
    }
    CPA_COMMIT;
    issueK(0); issueV(0);
    CPA_WAIT(1);
    __syncthreads();
    convQK(Qs, 0.125f);
    convQK(Ks, 1.f);
    __syncthreads();

    float runmax[2] = {-1e30f,-1e30f}, runsum[2] = {0.f,0.f};
    float pvacc[8][4];
    #pragma unroll
    for (int i=0;i<8;i++)
        #pragma unroll
        for (int r=0;r<4;r++) pvacc[i][r]=0.f;

    const int m0 = bm + wr + lr;

    for (int ct=0; ct<8; ct++){
        const int kb = ct*128;

        float sacc[16][4];
        #pragma unroll
        for (int i=0;i<16;i++)
            #pragma unroll
            for (int r=0;r<4;r++) sacc[i][r]=0.f;
        #pragma unroll
        for (int ch=0;ch<2;ch++){
            const uint32_t* Qc = (const uint32_t*)Qs + ch*128*AQS;
            const uint32_t* Kc = (const uint32_t*)Ks + ch*128*AQS;
            #pragma unroll
            for (int ks=0;ks<4;ks++){
                uint32_t af[4];
                const uint32_t* p = Qc + (wr+lr)*AQS + ks*8;
                af[0] = p[lc];
                af[1] = p[8*AQS + lc];
                af[2] = p[lc + 4];
                af[3] = p[8*AQS + lc + 4];
                #pragma unroll
                for (int nt=0;nt<16;nt++){
                    const uint32_t* q = Kc + (nt*8+lr)*AQS + ks*8;
                    uint32_t bf[2];
                    bf[0] = q[lc];
                    bf[1] = q[lc + 4];
                    mma8(sacc[nt], af, bf);
                }
            }
        }
        __syncthreads();
        if (ct < 7) issueK(ct+1);

        #pragma unroll
        for (int nt=0;nt<16;nt++){
            int n = kb + nt*8 + 2*lc;
            __stcs((float2*)(qko + (size_t)m0*Sd + n),     make_float2(sacc[nt][0], sacc[nt][1]));
            __stcs((float2*)(qko + (size_t)(m0+8)*Sd + n), make_float2(sacc[nt][2], sacc[nt][3]));
        }
        #pragma unroll
        for (int half=0;half<2;half++){
            float tm = -1e30f;
            #pragma unroll
            for (int nt=0;nt<16;nt++)
                tm = fmaxf(tm, fmaxf(sacc[nt][half*2], sacc[nt][half*2+1]));
            tm = fmaxf(tm, __shfl_xor_sync(0xffffffffu, tm, 1));
            tm = fmaxf(tm, __shfl_xor_sync(0xffffffffu, tm, 2));
            float mn = fmaxf(runmax[half], tm);
            float f = fexp(runmax[half] - mn);
            runmax[half] = mn;
            runsum[half] *= f;
            #pragma unroll
            for (int nt=0;nt<8;nt++){
                pvacc[nt][half*2+0] *= f;
                pvacc[nt][half*2+1] *= f;
            }
            float s = 0.f;
            #pragma unroll
            for (int nt=0;nt<16;nt++){
                float p0 = fexp(sacc[nt][half*2+0] - mn);
                float p1 = fexp(sacc[nt][half*2+1] - mn);
                s += p0 + p1;
                sacc[nt][half*2+0] = p0;
                sacc[nt][half*2+1] = p1;
            }
            s += __shfl_xor_sync(0xffffffffu, s, 1);
            s += __shfl_xor_sync(0xffffffffu, s, 2);
            runsum[half] += s;
        }
        if (ct < 7) CPA_WAIT(1); else CPA_WAIT(0);
        __syncthreads();
        convV();
        __syncthreads();

        #pragma unroll
        for (int ks=0;ks<16;ks++){
            uint32_t af[4];
            af[0] = f2tf(sacc[ks][0]);
            af[1] = f2tf(sacc[ks][2]);
            af[2] = f2tf(sacc[ks][1]);
            af[3] = f2tf(sacc[ks][3]);
            const uint32_t* pbase = (const uint32_t*)Vs + (ks>>2)*32*AVS + ((ks&3)*8)*AVS;
            #pragma unroll
            for (int nt=0;nt<8;nt++){
                const uint32_t* p = pbase + nt*8;
                uint32_t bf[2];
                bf[0] = p[lc*AVS + lr];
                bf[1] = p[(lc+4)*AVS + lr];
                mma8(pvacc[nt], af, bf);
            }
        }
        __syncthreads();
        if (ct < 7){
            issueV(ct+1);
            CPA_WAIT(1);
            __syncthreads();
            convQK(Ks, 1.f);
            __syncthreads();
        }
    }

    float* Cw = wv + (size_t)bq*Sd*Dd + h*DHd;
    float inv0 = 1.f / runsum[0], inv1 = 1.f / runsum[1];
    #pragma unroll
    for (int nt=0;nt<8;nt++){
        int n = nt*8 + 2*lc;
        *(float2*)(Cw + (size_t)m0*Dd + n)     = make_float2(pvacc[nt][0]*inv0, pvacc[nt][1]*inv0);
        *(float2*)(Cw + (size_t)(m0+8)*Dd + n) = make_float2(pvacc[nt][2]*inv1, pvacc[nt][3]*inv1);
    }
}

// ---- router ----
__global__ __launch_bounds__(256) void r_g(const float* __restrict__ cw,
                                           const float* __restrict__ pw, float* __restrict__ gpart){
    int idx = blockIdx.x*256 + threadIdx.x;
    int oz = blockIdx.y;
    const float* base = cw + (size_t)(oz*128)*3072 + idx;
    const float* pwb = pw + oz*128;
    float a0=0.f, a1=0.f;
    #pragma unroll 8
    for (int o=0;o<128;o+=2){
        a0 = fmaf(pwb[o],   base[(size_t)o*3072], a0);
        a1 = fmaf(pwb[o+1], base[(size_t)(o+1)*3072], a1);
    }
    gpart[oz*3072 + idx] = a0 + a1;
}
__global__ __launch_bounds__(256) void r_scores8(const float* __restrict__ x,
                                                 const float* __restrict__ gpart, float* __restrict__ scores){
    int m0 = blockIdx.x*8;
    int tid = threadIdx.x;
    __shared__ float gs[3072];
    __shared__ float sm[8];
    #pragma unroll
    for (int j=0;j<12;j++){
        int i = tid + j*256;
        float t = 0.f;
        #pragma unroll
        for (int oz=0;oz<8;oz++) t += gpart[oz*3072 + i];
        gs[i] = t;
    }
    __syncthreads();
    for (int r=0;r<8;r++){
        int m = m0 + r;
        int s = m & 1023;
        const float* x0 = x + (size_t)m*Dd;
        bool okm = (s > 0), okp = (s < 1023);
        float acc = 0.f;
        #pragma unroll
        for (int j=0;j<4;j++){
            int i = tid + j*256;
            float vm = okm ? x0[i - Dd] : 0.f;
            float v0 = x0[i];
            float vp = okp ? x0[i + Dd] : 0.f;
            const float* gg = gs + i*3;
            acc = fmaf(gg[0], vm, acc);
            acc = fmaf(gg[1], v0, acc);
            acc = fmaf(gg[2], vp, acc);
        }
        acc = warpRedSum(acc);
        if ((tid&31)==0) sm[tid>>5]=acc;
        __syncthreads();
        if (tid==0){
            float t = 0.f;
            #pragma unroll
            for (int i=0;i<8;i++) t += sm[i];
            scores[m] = t;
        }
        __syncthreads();
    }
}
__global__ void softmax_w(const float* __restrict__ scores, float* __restrict__ w){
    int b = blockIdx.x, tid = threadIdx.x;
    float4 v = *(const float4*)(scores + (size_t)b*Sd + tid*4);
    float m = fmaxf(fmaxf(v.x,v.y), fmaxf(v.z,v.w));
    m = warpRedMax(m);
    __shared__ float sm[8];
    __shared__ float gmax, gisum;
    if ((tid&31)==0) sm[tid>>5]=m;
    __syncthreads();
    if (tid==0){ float mm=sm[0]; for(int i=1;i<8;i++) mm=fmaxf(mm,sm[i]); gmax=mm; }
    __syncthreads();
    float e0=expf(v.x-gmax), e1=expf(v.y-gmax), e2=expf(v.z-gmax), e3=expf(v.w-gmax);
    float s = e0+e1+e2+e3;
    s = warpRedSum(s);
    if ((tid&31)==0) sm[tid>>5]=s;
    __syncthreads();
    if (tid==0){ float ss=0; for(int i=0;i<8;i++) ss+=sm[i]; gisum = 1.f/ss; }
    __syncthreads();
    *(float4*)(w + (size_t)b*Sd + tid*4) = make_float4(e0*gisum, e1*gisum, e2*gisum, e3*gisum);
}
__global__ __launch_bounds__(128) void r_xw(const float* __restrict__ x,
                                            const float* __restrict__ w, float* __restrict__ xwpart){
    int b = blockIdx.y;
    int sc = blockIdx.z;
    int i = blockIdx.x*128 + threadIdx.x;
    int s0 = sc*128;
    __shared__ float ws[130];
    for (int j = threadIdx.x; j < 130; j += 128){
        int s = s0 - 1 + j;
        ws[j] = ((unsigned)s < 1024u) ? w[(size_t)b*Sd + s] : 0.f;
    }
    __syncthreads();
    const float* xb = x + ((size_t)b*Sd + s0)*Dd + i;
    float a0=0.f, a1=0.f, a2=0.f;
    #pragma unroll 8
    for (int j=0;j<128;j++){
        float v = xb[(size_t)j*Dd];
        a0 = fmaf(ws[j+2], v, a0);
        a1 = fmaf(ws[j+1], v, a1);
        a2 = fmaf(ws[j],   v, a2);
    }
    float* o = xwpart + ((size_t)(sc*Bd + b))*3072 + i*3;
    o[0]=a0; o[1]=a1; o[2]=a2;
}
__global__ __launch_bounds__(256) void r_pooled(const float* __restrict__ cw,
                                                const float* __restrict__ cb,
                                                const float* __restrict__ xwpart, float* __restrict__ pooled){
    int b = blockIdx.y;
    int d = blockIdx.x*8 + (threadIdx.x >> 5);
    int lane = threadIdx.x & 31;
    __shared__ float sx[3072];
    for (int j = threadIdx.x; j < 3072; j += 256){
        float t = 0.f;
        #pragma unroll
        for (int sc=0;sc<8;sc++) t += xwpart[((size_t)(sc*Bd + b))*3072 + j];
        sx[j] = t;
    }
    __syncthreads();
    const float4* cr = (const float4*)(cw + (size_t)d*3072);
    float acc = 0.f;
    #pragma unroll
    for (int j=0;j<24;j++){
        float4 c = cr[lane + j*32];
        const float* s = sx + (lane + j*32)*4;
        acc += c.x*s[0] + c.y*s[1] + c.z*s[2] + c.w*s[3];
    }
    acc = warpRedSum(acc);
    if (lane == 0) pooled[b*Dd + d] = acc + cb[d];
}
__global__ void route_k(const float* __restrict__ pooled, const float* __restrict__ rw,
                        const float* __restrict__ rb, float* __restrict__ route){
    int b = blockIdx.x;
    int tid = threadIdx.x;
    int e = tid >> 5, lane = tid & 31;
    __shared__ float lg[8];
    float s=0.f;
    for (int d=lane; d<Dd; d+=32) s += pooled[b*Dd+d]*rw[e*Dd+d];
    s = warpRedSum(s);
    if (lane==0) lg[e] = s + rb[e];
    __syncthreads();
    if (tid==0){
        float mm=lg[0];
        for (int i=1;i<8;i++) mm=fmaxf(mm,lg[i]);
        float ex[8]; float ss=0.f;
        for (int i=0;i<8;i++){ ex[i]=expf(lg[i]-mm); ss+=ex[i]; }
        float inv = 1.f/ss;
        for (int i=0;i<8;i++) route[b*8+i]=ex[i]*inv;
    }
}

// ---- prep ----
__global__ void build_Bt3f(const float* __restrict__ B0, const float* __restrict__ B1,
                           const float* __restrict__ B2, float* __restrict__ Bt){
    int idx = blockIdx.x*blockDim.x + threadIdx.x;
    if (idx >= 3072*192) return;
    int n = idx / 192, c = idx - n*192;
    int p = n >> 10, pp = c >> 6;
    float val = 0.f;
    if (pp == p){
        int e = (c >> 3) & 7, r = c & 7;
        const float* Bp = (p==0) ? B0 : (p==1 ? B1 : B2);
        val = 2.f * Bp[(size_t)e*Dd*8 + (size_t)(n & 1023)*8 + r];
    }
    Bt[idx] = val;
}
__global__ void tr_loraB2x(const float* __restrict__ Bp, float* __restrict__ Bt){
    int idx = blockIdx.x*blockDim.x + threadIdx.x;
    if (idx >= Dd*64) return;
    int n = idx >> 6, e = (idx >> 3) & 7, r = idx & 7;
    Bt[idx] = 2.f * Bp[(size_t)e*Dd*8 + (size_t)n*8 + r];
}

// ---- host launcher (stream-forked; batch-split attn→o pipeline) ----
extern "C" void kernel_launch(void* const* d_in, const int* in_sizes, int n_in,
                              void* d_out, int out_size)
{
    (void)in_sizes; (void)n_in; (void)out_size;
    const float* x      = (const float*)d_in[0];
    const float* conv_w = (const float*)d_in[1];
    const float* conv_b = (const float*)d_in[2];
    const float* pool_w = (const float*)d_in[3];
    const float* pool_b = (const float*)d_in[4];
    const float* rlin_w = (const float*)d_in[5];
    const float* rlin_b = (const float*)d_in[6];
    const float* qW=(const float*)d_in[7],  *qb=(const float*)d_in[8];
    const float* qA=(const float*)d_in[9],  *qB=(const float*)d_in[10];
    const float* kW=(const float*)d_in[11], *kA=(const float*)d_in[12], *kB=(const float*)d_in[13];
    const float* vW=(const float*)d_in[14], *vb=(const float*)d_in[15];
    const float* vA=(const float*)d_in[16], *vB=(const float*)d_in[17];
    const float* oW=(const float*)d_in[18], *ob=(const float*)d_in[19];
    const float* oA=(const float*)d_in[20], *oB=(const float*)d_in[21];
    (void)pool_b;

    float* out = (float*)d_out;
    float* qk  = out + OUT_OFF;

    float *qkv,*wv,*h,*hpart,*Bt3f,*Bt,*gpart,*xwpart,*scores,*w,*pooled,*route;
    cudaGetSymbolAddress((void**)&qkv, g_qkv);
    cudaGetSymbolAddress((void**)&wv, g_wv);
    cudaGetSymbolAddress((void**)&h,  g_h);
    cudaGetSymbolAddress((void**)&hpart, g_hpart);
    cudaGetSymbolAddress((void**)&Bt3f, g_Bt3f);
    cudaGetSymbolAddress((void**)&Bt,  g_Bt);
    cudaGetSymbolAddress((void**)&gpart, g_gpart);
    cudaGetSymbolAddress((void**)&xwpart, g_xwpart);
    cudaGetSymbolAddress((void**)&scores, g_scores);
    cudaGetSymbolAddress((void**)&w,  g_wsm);
    cudaGetSymbolAddress((void**)&pooled, g_pooled);
    cudaGetSymbolAddress((void**)&route,  g_route);
    float* hpart2 = hpart + 4*(size_t)2048*64;   // disjoint scratch for half 2
    float* h2 = h + (size_t)2048*192;

    cudaFuncSetAttribute(mma_gemm, cudaFuncAttributeMaxDynamicSharedMemorySize, GEMM_SMEM);
    cudaFuncSetAttribute(attn_fused, cudaFuncAttributeMaxDynamicSharedMemorySize, ATTN_SMEM);

    cudaStream_t s2;
    cudaEvent_t ev1, ev2, ev3, ev4;
    cudaStreamCreateWithFlags(&s2, cudaStreamNonBlocking);
    cudaEventCreateWithFlags(&ev1, cudaEventDisableTiming);
    cudaEventCreateWithFlags(&ev2, cudaEventDisableTiming);
    cudaEventCreateWithFlags(&ev3, cudaEventDisableTiming);
    cudaEventCreateWithFlags(&ev4, cudaEventDisableTiming);

    // fork 1: s2 = prep + LoRA-A partials + base qkv; stream0 = router
    cudaEventRecord(ev1, 0);
    cudaStreamWaitEvent(s2, ev1, 0);

    build_Bt3f<<<(3072*192 + 255)/256, 256, 0, s2>>>(qB, kB, vB, Bt3f);
    tr_loraB2x<<<(Dd*64 + 255)/256, 256, 0, s2>>>(oB, Bt);
    mma_gemm<<<dim3(2,32,4), 256, GEMM_SMEM, s2>>>(x, qA, kA, vA, 6, hpart,
        Md, 192, 256, 1024, 1024, 192,
        x, 1024, x, 1024, 1<<30,
        (long long)Md*192,
        1.f, nullptr, nullptr, nullptr, nullptr, 0);
    mma_gemm<<<dim3(24,32,1), 256, GEMM_SMEM, s2>>>(x, qW, kW, vW, 10, qkv,
        Md, 3072, 1024, 1024, 1024, 3072,
        x, 1024, x, 1024, 1<<30,
        0,
        1.f, qb, nullptr, vb, nullptr, 0);

    r_g<<<dim3(12,8), 256>>>(conv_w, pool_w, gpart);
    r_scores8<<<Md/8, 256>>>(x, gpart, scores);
    softmax_w<<<Bd, 256>>>(scores, w);
    r_xw<<<dim3(8,Bd,8), 128>>>(x, w, xwpart);
    r_pooled<<<dim3(128,Bd), 256>>>(conv_w, conv_b, xwpart, pooled);
    route_k<<<Bd, 256>>>(pooled, rlin_w, rlin_b, route);

    cudaEventRecord(ev2, s2);
    cudaStreamWaitEvent(0, ev2, 0);

    red_h<<<(Md*192 + 255)/256, 256>>>(hpart, route, h, 192, Md, 0);
    mma_gemm<<<dim3(24,32,1), 256, GEMM_SMEM>>>(h, Bt3f, Bt3f, Bt3f, -1, qkv,
        Md, 3072, 192, 192, 192, 3072,
        h, 192, h, 192, 1<<30,
        0,
        1.f, nullptr, nullptr, nullptr, nullptr, 1);

    // attn half 1 (bq 0,1)
    attn_fused<<<dim3(8,32), 256, ATTN_SMEM>>>(qkv, qk, wv);
    cudaEventRecord(ev3, 0);
    // attn half 2 (bq 2,3) via pointer offsets
    attn_fused<<<dim3(8,32), 256, ATTN_SMEM>>>(qkv + (size_t)2*Sd*3072,
                                               qk + (size_t)32*Sd*Sd,
                                               wv + (size_t)2*Sd*Dd);

    // s2: o-chain for rows 0..2047, overlapping attn half 2
    cudaStreamWaitEvent(s2, ev3, 0);
    mma_gemm<<<dim3(1,16,4), 256, GEMM_SMEM, s2>>>(wv, oA, oA, oA, -1, hpart,
        2048, 64, 256, 1024, 1024, 64,
        wv, 1024, wv, 1024, 1<<30,
        (long long)2048*64,
        1.f, nullptr, nullptr, nullptr, nullptr, 0);
    red_h<<<(2048*64 + 255)/256, 256, 0, s2>>>(hpart, route, h, 64, 2048, 0);
    mma_gemm<<<dim3(8,16,1), 256, GEMM_SMEM, s2>>>(wv, oW, oW, oW, -1, out,
        2048, 1024, 1024, 1024, 1024, 1024,
        wv, 1024, wv, 1024, 1<<30,
        0,
        1.f, ob, nullptr, nullptr, nullptr, 0);
    mma_gemm<<<dim3(8,16,1), 256, GEMM_SMEM, s2>>>(h, Bt, Bt, Bt, -1, out,
        2048, 1024, 64, 192, 64, 1024,
        h, 192, h, 192, 1<<30,
        0,
        1.f, nullptr, nullptr, nullptr, nullptr, 1);
    cudaEventRecord(ev4, s2);

    // stream0: o-chain for rows 2048..4095 (after attn half 2)
    mma_gemm<<<dim3(1,16,4), 256, GEMM_SMEM>>>(wv + (size_t)2048*1024, oA, oA, oA, -1, hpart2,
        2048, 64, 256, 1024, 1024, 64,
        wv + (size_t)2048*1024, 1024, wv + (size_t)2048*1024, 1024, 1<<30,
        (long long)2048*64,
        1.f, nullptr, nullptr, nullptr, nullptr, 0);
    red_h<<<(2048*64 + 255)/256, 256>>>(hpart2, route, h2, 64, 2048, 2);
    mma_gemm<<<dim3(8,16,1), 256, GEMM_SMEM>>>(wv + (size_t)2048*1024, oW, oW, oW, -1, out + (size_t)2048*1024,
        2048, 1024, 1024, 1024, 1024, 1024,
        wv + (size_t)2048*1024, 1024, wv + (size_t)2048*1024, 1024, 1<<30,
        0,
        1.f, ob, nullptr, nullptr, nullptr, 0);
    mma_gemm<<<dim3(8,16,1), 256, GEMM_SMEM>>>(h2, Bt, Bt, Bt, -1, out + (size_t)2048*1024,
        2048, 1024, 64, 192, 64, 1024,
        h2, 192, h2, 192, 1<<30,
        0,
        1.f, nullptr, nullptr, nullptr, nullptr, 1);

    cudaStreamWaitEvent(0, ev4, 0);
}

// round 17
// speedup vs baseline: 1.0729x; 1.0200x over previous
#include <cuda_runtime.h>
#include <cstdint>
#include <cstddef>

#define Bd 4
#define Sd 1024
#define Dd 1024
#define Hd 16
#define DHd 64
#define Md (Bd*Sd)
#define OUT_OFF ((size_t)Bd*Sd*Dd)

__device__ float g_qkv[(size_t)Md*3072];
__device__ float g_wv[Md*Dd];
__device__ float g_h[Md*192];
__device__ float g_hpart[4*(size_t)Md*192];
__device__ float g_Bt3f[3072*192];
__device__ float g_Bt[Dd*64];
__device__ float g_gpart[8*3072];
__device__ float g_xwpart[8*Bd*3072];
__device__ float g_scores[Md];
__device__ float g_wsm[Md];
__device__ float g_pooled[Bd*Dd];
__device__ float g_route[Bd*8];

__device__ __forceinline__ float warpRedSum(float v){
    #pragma unroll
    for (int o=16;o;o>>=1) v += __shfl_xor_sync(0xffffffffu, v, o);
    return v;
}
__device__ __forceinline__ float warpRedMax(float v){
    #pragma unroll
    for (int o=16;o;o>>=1) v = fmaxf(v, __shfl_xor_sync(0xffffffffu, v, o));
    return v;
}
__device__ __forceinline__ float fexp(float x){
    float t = x * 1.4426950408889634f;
    t = fmaxf(t, -126.0f);
    float ti = floorf(t);
    float f = t - ti;
    float p = 1.5403530393381608e-4f;
    p = fmaf(p, f, 1.3333558146428443e-3f);
    p = fmaf(p, f, 9.6181291076284770e-3f);
    p = fmaf(p, f, 5.5504108664821580e-2f);
    p = fmaf(p, f, 2.4022650695910070e-1f);
    p = fmaf(p, f, 6.9314718055994530e-1f);
    p = fmaf(p, f, 1.0f);
    return __int_as_float(((int)ti + 127) << 23) * p;
}
__device__ __forceinline__ uint32_t f2tf(float f){
    uint32_t r; asm("cvt.rna.tf32.f32 %0, %1;" : "=r"(r) : "f"(f)); return r;
}
__device__ __forceinline__ void mma8(float* d, const uint32_t* a, const uint32_t* b){
    asm volatile("mma.sync.aligned.m16n8k8.row.col.f32.tf32.tf32.f32 "
        "{%0,%1,%2,%3}, {%4,%5,%6,%7}, {%8,%9}, {%0,%1,%2,%3};"
        : "+f"(d[0]),"+f"(d[1]),"+f"(d[2]),"+f"(d[3])
        : "r"(a[0]),"r"(a[1]),"r"(a[2]),"r"(a[3]), "r"(b[0]),"r"(b[1]));
}
__device__ __forceinline__ uint32_t smem_u32(const void* p){
    uint32_t a; asm("{ .reg .u64 t; cvta.to.shared.u64 t, %1; cvt.u32.u64 %0, t; }" : "=r"(a) : "l"(p));
    return a;
}
__device__ __forceinline__ void cpa16(uint32_t dst, const void* src, int ok){
    asm volatile("cp.async.cg.shared.global [%0], [%1], 16, %2;"
        :: "r"(dst), "l"(src), "r"(ok ? 16 : 0));
}
#define CPA_COMMIT asm volatile("cp.async.commit_group;" ::: "memory")
#define CPA_WAIT(n) asm volatile("cp.async.wait_group %0;" :: "n"(n) : "memory")

// ---- tf32 mma.sync GEMM; prologue-hoisted addressing, dead split-K source removed ----
#define GSTRIDE 36
#define GEMM_SMEM (4*128*GSTRIDE*4)
__global__ __launch_bounds__(256,2)
void mma_gemm(const float* __restrict__ A,
              const float* __restrict__ B0, const float* __restrict__ B1,
              const float* __restrict__ B2s, int segShift,
              float* __restrict__ C,
              int M, int N, int K, int lda, int ldb, int ldc,
              long long sCz,
              float alpha,
              const float* __restrict__ bias0, const float* __restrict__ bias1,
              const float* __restrict__ bias2,
              const float* __restrict__ route, int addC)
{
    extern __shared__ __align__(16) float sm[];
    float* As = sm;
    float* Bs = sm + 2*128*GSTRIDE;

    const int tid = threadIdx.x, wid = tid >> 5, lane = tid & 31;
    const int wm = wid >> 2, wn = wid & 3;
    const int lr = lane >> 2, lc = lane & 3;
    const int bm = blockIdx.y*128, bn = blockIdx.x*128;
    const int zc = blockIdx.z;
    const int kzbase = zc * K;
    C += (size_t)zc * sCz;

    const int row = tid >> 3, c4 = (tid & 7) << 2;
    const float* Ab = A + (size_t)bm*lda;
    const int nch = K >> 5;
    const int segMask = (segShift >= 0) ? ((1 << segShift) - 1) : -1;
    const uint32_t sA = smem_u32(As), sB = smem_u32(Bs);

    // prologue-hoisted per-j addressing
    int aoff[4];
    const float* bRow[4];
    int bok[4];
    #pragma unroll
    for (int j=0;j<4;j++){
        int rr = row + j*32;
        aoff[j] = rr * lda;
        int n = bn + rr;
        bok[j] = (n < N);
        int nn = bok[j] ? n : 0;
        if (segShift >= 0){
            int sel = nn >> segShift;
            const float* Bp = (sel==0) ? B0 : (sel==1 ? B1 : B2s);
            bRow[j] = Bp + (size_t)(nn & segMask)*ldb;
        } else {
            bRow[j] = B0 + (size_t)nn*ldb;
        }
    }

    auto issue = [&](int c){
        int buf = c & 1;
        int kk = kzbase + (c << 5) + c4;
        #pragma unroll
        for (int j=0;j<4;j++){
            int rr = row + j*32;
            cpa16(sA + (uint32_t)((buf*128 + rr)*GSTRIDE + c4)*4, Ab + aoff[j] + kk, 1);
            cpa16(sB + (uint32_t)((buf*128 + rr)*GSTRIDE + c4)*4, bRow[j] + kk, bok[j]);
        }
        CPA_COMMIT;
    };

    float acc[4][4][4];
    #pragma unroll
    for (int i=0;i<4;i++)
        #pragma unroll
        for (int j=0;j<4;j++)
            #pragma unroll
            for (int r=0;r<4;r++) acc[i][j][r]=0.f;

    issue(0);
    if (nch > 1){ issue(1); CPA_WAIT(1); } else CPA_WAIT(0);
    __syncthreads();

    for (int c = 0; c < nch; c++){
        const float* Ac = As + (c&1)*128*GSTRIDE;
        const float* Bc = Bs + (c&1)*128*GSTRIDE;
        #pragma unroll
        for (int ks=0; ks<4; ks++){
            uint32_t af[4][4], bf[4][2];
            #pragma unroll
            for (int mt=0; mt<4; mt++){
                const float* p = Ac + (wm*64 + mt*16)*GSTRIDE + ks*8;
                af[mt][0] = f2tf(p[lr*GSTRIDE + lc]);
                af[mt][1] = f2tf(p[(lr+8)*GSTRIDE + lc]);
                af[mt][2] = f2tf(p[lr*GSTRIDE + lc + 4]);
                af[mt][3] = f2tf(p[(lr+8)*GSTRIDE + lc + 4]);
            }
            #pragma unroll
            for (int nt=0; nt<4; nt++){
                const float* p = Bc + (wn*32 + nt*8)*GSTRIDE + ks*8;
                bf[nt][0] = f2tf(p[lr*GSTRIDE + lc]);
                bf[nt][1] = f2tf(p[lr*GSTRIDE + lc + 4]);
            }
            #pragma unroll
            for (int mt=0; mt<4; mt++)
                #pragma unroll
                for (int nt=0; nt<4; nt++)
                    mma8(acc[mt][nt], af[mt], bf[nt]);
        }
        __syncthreads();
        if (c+2 < nch) issue(c+2);
        if (c+1 < nch){
            if (c+2 < nch) CPA_WAIT(1); else CPA_WAIT(0);
            __syncthreads();
        }
    }

    #pragma unroll
    for (int mt=0; mt<4; mt++){
        #pragma unroll
        for (int nt=0; nt<4; nt++){
            int n = bn + wn*32 + nt*8 + 2*lc;
            if (n >= N) continue;
            int m0 = bm + wm*64 + mt*16 + lr;
            float bv0 = 0.f, bv1 = 0.f;
            if (bias0){
                if (segShift >= 0){
                    int sel = n >> segShift;
                    const float* bp = (sel==0) ? bias0 : (sel==1 ? bias1 : bias2);
                    if (bp){ bv0 = bp[n & segMask]; bv1 = bp[(n+1) & segMask]; }
                } else { bv0 = bias0[n]; bv1 = bias0[n+1]; }
            }
            #pragma unroll
            for (int half=0; half<2; half++){
                int m = m0 + half*8;
                float v0 = alpha*acc[mt][nt][half*2+0];
                float v1 = alpha*acc[mt][nt][half*2+1];
                if (route){
                    float rs = route[((m >> 10) << 3) + ((n & 63) >> 3)];
                    v0 *= rs; v1 *= rs;
                }
                v0 += bv0; v1 += bv1;
                float2* cp = (float2*)(C + (size_t)m*ldc + n);
                if (addC){ float2 o = *cp; v0 += o.x; v1 += o.y; }
                *cp = make_float2(v0, v1);
            }
        }
    }
}

// reduce split-K partials + apply route
__global__ void red_h(const float* __restrict__ hp, const float* __restrict__ route,
                      float* __restrict__ h, int C){
    int idx = blockIdx.x*256 + threadIdx.x;
    if (idx >= Md*C) return;
    int m = idx / C, c = idx - m*C;
    size_t stride = (size_t)Md*C;
    float s = hp[idx] + hp[stride + idx] + hp[2*stride + idx] + hp[3*stride + idx];
    h[(size_t)m*192 + c] = s * route[((m >> 10) << 3) + ((c & 63) >> 3)];
}

// ---- fused flash attention (R13 version, unchanged) ----
#define AQS 36
#define AVS 72
#define ATTN_SMEM ((2*128*AQS + 2*128*AQS + 4*32*AVS)*4)
__global__ __launch_bounds__(256,2) void attn_fused(
    const float* __restrict__ qkv, float* __restrict__ qk, float* __restrict__ wv)
{
    extern __shared__ __align__(16) float dsm[];
    float* Qs = dsm;
    float* Ks = dsm + 2*128*AQS;
    float* Vs = Ks + 2*128*AQS;

    const int z = blockIdx.y;
    const int bq = z >> 4, h = z & 15;
    const int bm = blockIdx.x * 128;
    const float* Qg = qkv + (size_t)bq*Sd*3072 + h*64;
    const float* Kg = Qg + 1024;
    const float* Vg = Qg + 2048;
    float* qko = qk + (size_t)z*Sd*Sd;

    const int tid = threadIdx.x, wid = tid >> 5, lane = tid & 31;
    const int lr = lane >> 2, lc = lane & 3;
    const int wr = wid * 16;
    const int rr0 = tid >> 3, c4 = (tid & 7) << 2;
    const uint32_t sQ = smem_u32(Qs), sK = smem_u32(Ks), sV = smem_u32(Vs);

    auto issueK = [&](int ct){
        int kb = ct << 7;
        #pragma unroll
        for (int j=0;j<4;j++){
            int rr = rr0 + j*32;
            #pragma unroll
            for (int ch=0;ch<2;ch++)
                cpa16(sK + (uint32_t)(((ch*128 + rr)*AQS + c4)*4),
                      Kg + (size_t)(kb+rr)*3072 + ch*32 + c4, 1);
        }
        CPA_COMMIT;
    };
    auto issueV = [&](int ct){
        int kb = ct << 7;
        #pragma unroll
        for (int j=0;j<8;j++){
            int idx = tid + (j << 8);
            int vk = idx >> 4, vc4 = (idx & 15) << 2;
            int w8 = vk & 7;
            int slot = (vk & ~7) | (w8 >> 1) | ((w8 & 1) << 2);
            cpa16(sV + (uint32_t)((((slot>>5)*32 + (slot&31))*AVS + vc4)*4),
                  Vg + (size_t)(kb+vk)*3072 + vc4, 1);
        }
        CPA_COMMIT;
    };
    auto convQK = [&](float* base, float scale){
        #pragma unroll
        for (int j=0;j<4;j++){
            int rr = rr0 + j*32;
            #pragma unroll
            for (int ch=0;ch<2;ch++){
                float4* p = (float4*)(base + (ch*128 + rr)*AQS + c4);
                float4 v = *p;
                uint4 u;
                u.x = f2tf(v.x*scale); u.y = f2tf(v.y*scale);
                u.z = f2tf(v.z*scale); u.w = f2tf(v.w*scale);
                *(uint4*)p = u;
            }
        }
    };
    auto convV = [&](){
        #pragma unroll
        for (int j=0;j<8;j++){
            int idx = tid + (j << 8);
            int vk = idx >> 4, vc4 = (idx & 15) << 2;
            float4* p = (float4*)(Vs + (vk>>5)*32*AVS + (vk&31)*AVS + vc4);
            float4 v = *p;
            uint4 u;
            u.x = f2tf(v.x); u.y = f2tf(v.y); u.z = f2tf(v.z); u.w = f2tf(v.w);
            *(uint4*)p = u;
        }
    };

    #pragma unroll
    for (int j=0;j<4;j++){
        int rr = rr0 + j*32;
        #pragma unroll
        for (int ch=0;ch<2;ch++)
            cpa16(sQ + (uint32_t)(((ch*128 + rr)*AQS + c4)*4),
                  Qg + (size_t)(bm+rr)*3072 + ch*32 + c4, 1);
    }
    CPA_COMMIT;
    issueK(0); issueV(0);
    CPA_WAIT(1);
    __syncthreads();
    convQK(Qs, 0.125f);
    convQK(Ks, 1.f);
    __syncthreads();

    float runmax[2] = {-1e30f,-1e30f}, runsum[2] = {0.f,0.f};
    float pvacc[8][4];
    #pragma unroll
    for (int i=0;i<8;i++)
        #pragma unroll
        for (int r=0;r<4;r++) pvacc[i][r]=0.f;

    const int m0 = bm + wr + lr;

    for (int ct=0; ct<8; ct++){
        const int kb = ct*128;

        float sacc[16][4];
        #pragma unroll
        for (int i=0;i<16;i++)
            #pragma unroll
            for (int r=0;r<4;r++) sacc[i][r]=0.f;
        #pragma unroll
        for (int ch=0;ch<2;ch++){
            const uint32_t* Qc = (const uint32_t*)Qs + ch*128*AQS;
            const uint32_t* Kc = (const uint32_t*)Ks + ch*128*AQS;
            #pragma unroll
            for (int ks=0;ks<4;ks++){
                uint32_t af[4];
                const uint32_t* p = Qc + (wr+lr)*AQS + ks*8;
                af[0] = p[lc];
                af[1] = p[8*AQS + lc];
                af[2] = p[lc + 4];
                af[3] = p[8*AQS + lc + 4];
                #pragma unroll
                for (int nt=0;nt<16;nt++){
                    const uint32_t* q = Kc + (nt*8+lr)*AQS + ks*8;
                    uint32_t bf[2];
                    bf[0] = q[lc];
                    bf[1] = q[lc + 4];
                    mma8(sacc[nt], af, bf);
                }
            }
        }
        __syncthreads();
        if (ct < 7) issueK(ct+1);

        #pragma unroll
        for (int nt=0;nt<16;nt++){
            int n = kb + nt*8 + 2*lc;
            __stcs((float2*)(qko + (size_t)m0*Sd + n),     make_float2(sacc[nt][0], sacc[nt][1]));
            __stcs((float2*)(qko + (size_t)(m0+8)*Sd + n), make_float2(sacc[nt][2], sacc[nt][3]));
        }
        #pragma unroll
        for (int half=0;half<2;half++){
            float tm = -1e30f;
            #pragma unroll
            for (int nt=0;nt<16;nt++)
                tm = fmaxf(tm, fmaxf(sacc[nt][half*2], sacc[nt][half*2+1]));
            tm = fmaxf(tm, __shfl_xor_sync(0xffffffffu, tm, 1));
            tm = fmaxf(tm, __shfl_xor_sync(0xffffffffu, tm, 2));
            float mn = fmaxf(runmax[half], tm);
            float f = fexp(runmax[half] - mn);
            runmax[half] = mn;
            runsum[half] *= f;
            #pragma unroll
            for (int nt=0;nt<8;nt++){
                pvacc[nt][half*2+0] *= f;
                pvacc[nt][half*2+1] *= f;
            }
            float s = 0.f;
            #pragma unroll
            for (int nt=0;nt<16;nt++){
                float p0 = fexp(sacc[nt][half*2+0] - mn);
                float p1 = fexp(sacc[nt][half*2+1] - mn);
                s += p0 + p1;
                sacc[nt][half*2+0] = p0;
                sacc[nt][half*2+1] = p1;
            }
            s += __shfl_xor_sync(0xffffffffu, s, 1);
            s += __shfl_xor_sync(0xffffffffu, s, 2);
            runsum[half] += s;
        }
        if (ct < 7) CPA_WAIT(1); else CPA_WAIT(0);
        __syncthreads();
        convV();
        __syncthreads();

        #pragma unroll
        for (int ks=0;ks<16;ks++){
            uint32_t af[4];
            af[0] = f2tf(sacc[ks][0]);
            af[1] = f2tf(sacc[ks][2]);
            af[2] = f2tf(sacc[ks][1]);
            af[3] = f2tf(sacc[ks][3]);
            const uint32_t* pbase = (const uint32_t*)Vs + (ks>>2)*32*AVS + ((ks&3)*8)*AVS;
            #pragma unroll
            for (int nt=0;nt<8;nt++){
                const uint32_t* p = pbase + nt*8;
                uint32_t bf[2];
                bf[0] = p[lc*AVS + lr];
                bf[1] = p[(lc+4)*AVS + lr];
                mma8(pvacc[nt], af, bf);
            }
        }
        __syncthreads();
        if (ct < 7){
            issueV(ct+1);
            CPA_WAIT(1);
            __syncthreads();
            convQK(Ks, 1.f);
            __syncthreads();
        }
    }

    float* Cw = wv + (size_t)bq*Sd*Dd + h*DHd;
    float inv0 = 1.f / runsum[0], inv1 = 1.f / runsum[1];
    #pragma unroll
    for (int nt=0;nt<8;nt++){
        int n = nt*8 + 2*lc;
        *(float2*)(Cw + (size_t)m0*Dd + n)     = make_float2(pvacc[nt][0]*inv0, pvacc[nt][1]*inv0);
        *(float2*)(Cw + (size_t)(m0+8)*Dd + n) = make_float2(pvacc[nt][2]*inv1, pvacc[nt][3]*inv1);
    }
}

// ---- router ----
__global__ __launch_bounds__(256) void r_g(const float* __restrict__ cw,
                                           const float* __restrict__ pw, float* __restrict__ gpart){
    int idx = blockIdx.x*256 + threadIdx.x;
    int oz = blockIdx.y;
    const float* base = cw + (size_t)(oz*128)*3072 + idx;
    const float* pwb = pw + oz*128;
    float a0=0.f, a1=0.f;
    #pragma unroll 8
    for (int o=0;o<128;o+=2){
        a0 = fmaf(pwb[o],   base[(size_t)o*3072], a0);
        a1 = fmaf(pwb[o+1], base[(size_t)(o+1)*3072], a1);
    }
    gpart[oz*3072 + idx] = a0 + a1;
}
__global__ __launch_bounds__(256) void r_scores8(const float* __restrict__ x,
                                                 const float* __restrict__ gpart, float* __restrict__ scores){
    int m0 = blockIdx.x*8;
    int tid = threadIdx.x;
    __shared__ float gs[3072];
    __shared__ float sm[8];
    #pragma unroll
    for (int j=0;j<12;j++){
        int i = tid + j*256;
        float t = 0.f;
        #pragma unroll
        for (int oz=0;oz<8;oz++) t += gpart[oz*3072 + i];
        gs[i] = t;
    }
    __syncthreads();
    for (int r=0;r<8;r++){
        int m = m0 + r;
        int s = m & 1023;
        const float* x0 = x + (size_t)m*Dd;
        bool okm = (s > 0), okp = (s < 1023);
        float acc = 0.f;
        #pragma unroll
        for (int j=0;j<4;j++){
            int i = tid + j*256;
            float vm = okm ? x0[i - Dd] : 0.f;
            float v0 = x0[i];
            float vp = okp ? x0[i + Dd] : 0.f;
            const float* gg = gs + i*3;
            acc = fmaf(gg[0], vm, acc);
            acc = fmaf(gg[1], v0, acc);
            acc = fmaf(gg[2], vp, acc);
        }
        acc = warpRedSum(acc);
        if ((tid&31)==0) sm[tid>>5]=acc;
        __syncthreads();
        if (tid==0){
            float t = 0.f;
            #pragma unroll
            for (int i=0;i<8;i++) t += sm[i];
            scores[m] = t;
        }
        __syncthreads();
    }
}
__global__ void softmax_w(const float* __restrict__ scores, float* __restrict__ w){
    int b = blockIdx.x, tid = threadIdx.x;
    float4 v = *(const float4*)(scores + (size_t)b*Sd + tid*4);
    float m = fmaxf(fmaxf(v.x,v.y), fmaxf(v.z,v.w));
    m = warpRedMax(m);
    __shared__ float sm[8];
    __shared__ float gmax, gisum;
    if ((tid&31)==0) sm[tid>>5]=m;
    __syncthreads();
    if (tid==0){ float mm=sm[0]; for(int i=1;i<8;i++) mm=fmaxf(mm,sm[i]); gmax=mm; }
    __syncthreads();
    float e0=expf(v.x-gmax), e1=expf(v.y-gmax), e2=expf(v.z-gmax), e3=expf(v.w-gmax);
    float s = e0+e1+e2+e3;
    s = warpRedSum(s);
    if ((tid&31)==0) sm[tid>>5]=s;
    __syncthreads();
    if (tid==0){ float ss=0; for(int i=0;i<8;i++) ss+=sm[i]; gisum = 1.f/ss; }
    __syncthreads();
    *(float4*)(w + (size_t)b*Sd + tid*4) = make_float4(e0*gisum, e1*gisum, e2*gisum, e3*gisum);
}
__global__ __launch_bounds__(128) void r_xw(const float* __restrict__ x,
                                            const float* __restrict__ w, float* __restrict__ xwpart){
    int b = blockIdx.y;
    int sc = blockIdx.z;
    int i = blockIdx.x*128 + threadIdx.x;
    int s0 = sc*128;
    __shared__ float ws[130];
    for (int j = threadIdx.x; j < 130; j += 128){
        int s = s0 - 1 + j;
        ws[j] = ((unsigned)s < 1024u) ? w[(size_t)b*Sd + s] : 0.f;
    }
    __syncthreads();
    const float* xb = x + ((size_t)b*Sd + s0)*Dd + i;
    float a0=0.f, a1=0.f, a2=0.f;
    #pragma unroll 8
    for (int j=0;j<128;j++){
        float v = xb[(size_t)j*Dd];
        a0 = fmaf(ws[j+2], v, a0);
        a1 = fmaf(ws[j+1], v, a1);
        a2 = fmaf(ws[j],   v, a2);
    }
    float* o = xwpart + ((size_t)(sc*Bd + b))*3072 + i*3;
    o[0]=a0; o[1]=a1; o[2]=a2;
}
__global__ __launch_bounds__(256) void r_pooled(const float* __restrict__ cw,
                                                const float* __restrict__ cb,
                                                const float* __restrict__ xwpart, float* __restrict__ pooled){
    int b = blockIdx.y;
    int d = blockIdx.x*8 + (threadIdx.x >> 5);
    int lane = threadIdx.x & 31;
    __shared__ float sx[3072];
    for (int j = threadIdx.x; j < 3072; j += 256){
        float t = 0.f;
        #pragma unroll
        for (int sc=0;sc<8;sc++) t += xwpart[((size_t)(sc*Bd + b))*3072 + j];
        sx[j] = t;
    }
    __syncthreads();
    const float4* cr = (const float4*)(cw + (size_t)d*3072);
    float acc = 0.f;
    #pragma unroll
    for (int j=0;j<24;j++){
        float4 c = cr[lane + j*32];
        const float* s = sx + (lane + j*32)*4;
        acc += c.x*s[0] + c.y*s[1] + c.z*s[2] + c.w*s[3];
    }
    acc = warpRedSum(acc);
    if (lane == 0) pooled[b*Dd + d] = acc + cb[d];
}
__global__ void route_k(const float* __restrict__ pooled, const float* __restrict__ rw,
                        const float* __restrict__ rb, float* __restrict__ route){
    int b = blockIdx.x;
    int tid = threadIdx.x;
    int e = tid >> 5, lane = tid & 31;
    __shared__ float lg[8];
    float s=0.f;
    for (int d=lane; d<Dd; d+=32) s += pooled[b*Dd+d]*rw[e*Dd+d];
    s = warpRedSum(s);
    if (lane==0) lg[e] = s + rb[e];
    __syncthreads();
    if (tid==0){
        float mm=lg[0];
        for (int i=1;i<8;i++) mm=fmaxf(mm,lg[i]);
        float ex[8]; float ss=0.f;
        for (int i=0;i<8;i++){ ex[i]=expf(lg[i]-mm); ss+=ex[i]; }
        float inv = 1.f/ss;
        for (int i=0;i<8;i++) route[b*8+i]=ex[i]*inv;
    }
}

// ---- prep ----
__global__ void build_Bt3f(const float* __restrict__ B0, const float* __restrict__ B1,
                           const float* __restrict__ B2, float* __restrict__ Bt){
    int idx = blockIdx.x*blockDim.x + threadIdx.x;
    if (idx >= 3072*192) return;
    int n = idx / 192, c = idx - n*192;
    int p = n >> 10, pp = c >> 6;
    float val = 0.f;
    if (pp == p){
        int e = (c >> 3) & 7, r = c & 7;
        const float* Bp = (p==0) ? B0 : (p==1 ? B1 : B2);
        val = 2.f * Bp[(size_t)e*Dd*8 + (size_t)(n & 1023)*8 + r];
    }
    Bt[idx] = val;
}
__global__ void tr_loraB2x(const float* __restrict__ Bp, float* __restrict__ Bt){
    int idx = blockIdx.x*blockDim.x + threadIdx.x;
    if (idx >= Dd*64) return;
    int n = idx >> 6, e = (idx >> 3) & 7, r = idx & 7;
    Bt[idx] = 2.f * Bp[(size_t)e*Dd*8 + (size_t)n*8 + r];
}

// ---- host launcher (R13 structure) ----
extern "C" void kernel_launch(void* const* d_in, const int* in_sizes, int n_in,
                              void* d_out, int out_size)
{
    (void)in_sizes; (void)n_in; (void)out_size;
    const float* x      = (const float*)d_in[0];
    const float* conv_w = (const float*)d_in[1];
    const float* conv_b = (const float*)d_in[2];
    const float* pool_w = (const float*)d_in[3];
    const float* pool_b = (const float*)d_in[4];
    const float* rlin_w = (const float*)d_in[5];
    const float* rlin_b = (const float*)d_in[6];
    const float* qW=(const float*)d_in[7],  *qb=(const float*)d_in[8];
    const float* qA=(const float*)d_in[9],  *qB=(const float*)d_in[10];
    const float* kW=(const float*)d_in[11], *kA=(const float*)d_in[12], *kB=(const float*)d_in[13];
    const float* vW=(const float*)d_in[14], *vb=(const float*)d_in[15];
    const float* vA=(const float*)d_in[16], *vB=(const float*)d_in[17];
    const float* oW=(const float*)d_in[18], *ob=(const float*)d_in[19];
    const float* oA=(const float*)d_in[20], *oB=(const float*)d_in[21];
    (void)pool_b;

    float* out = (float*)d_out;
    float* qk  = out + OUT_OFF;

    float *qkv,*wv,*h,*hpart,*Bt3f,*Bt,*gpart,*xwpart,*scores,*w,*pooled,*route;
    cudaGetSymbolAddress((void**)&qkv, g_qkv);
    cudaGetSymbolAddress((void**)&wv, g_wv);
    cudaGetSymbolAddress((void**)&h,  g_h);
    cudaGetSymbolAddress((void**)&hpart, g_hpart);
    cudaGetSymbolAddress((void**)&Bt3f, g_Bt3f);
    cudaGetSymbolAddress((void**)&Bt,  g_Bt);
    cudaGetSymbolAddress((void**)&gpart, g_gpart);
    cudaGetSymbolAddress((void**)&xwpart, g_xwpart);
    cudaGetSymbolAddress((void**)&scores, g_scores);
    cudaGetSymbolAddress((void**)&w,  g_wsm);
    cudaGetSymbolAddress((void**)&pooled, g_pooled);
    cudaGetSymbolAddress((void**)&route,  g_route);

    cudaFuncSetAttribute(mma_gemm, cudaFuncAttributeMaxDynamicSharedMemorySize, GEMM_SMEM);
    cudaFuncSetAttribute(attn_fused, cudaFuncAttributeMaxDynamicSharedMemorySize, ATTN_SMEM);

    cudaStream_t s2;
    cudaEvent_t ev1, ev2, ev3, ev4;
    cudaStreamCreateWithFlags(&s2, cudaStreamNonBlocking);
    cudaEventCreateWithFlags(&ev1, cudaEventDisableTiming);
    cudaEventCreateWithFlags(&ev2, cudaEventDisableTiming);
    cudaEventCreateWithFlags(&ev3, cudaEventDisableTiming);
    cudaEventCreateWithFlags(&ev4, cudaEventDisableTiming);

    cudaEventRecord(ev1, 0);
    cudaStreamWaitEvent(s2, ev1, 0);

    build_Bt3f<<<(3072*192 + 255)/256, 256, 0, s2>>>(qB, kB, vB, Bt3f);
    tr_loraB2x<<<(Dd*64 + 255)/256, 256, 0, s2>>>(oB, Bt);
    mma_gemm<<<dim3(2,32,4), 256, GEMM_SMEM, s2>>>(x, qA, kA, vA, 6, hpart,
        Md, 192, 256, 1024, 1024, 192,
        (long long)Md*192,
        1.f, nullptr, nullptr, nullptr, nullptr, 0);
    mma_gemm<<<dim3(24,32,1), 256, GEMM_SMEM, s2>>>(x, qW, kW, vW, 10, qkv,
        Md, 3072, 1024, 1024, 1024, 3072,
        0,
        1.f, qb, nullptr, vb, nullptr, 0);

    r_g<<<dim3(12,8), 256>>>(conv_w, pool_w, gpart);
    r_scores8<<<Md/8, 256>>>(x, gpart, scores);
    softmax_w<<<Bd, 256>>>(scores, w);
    r_xw<<<dim3(8,Bd,8), 128>>>(x, w, xwpart);
    r_pooled<<<dim3(128,Bd), 256>>>(conv_w, conv_b, xwpart, pooled);
    route_k<<<Bd, 256>>>(pooled, rlin_w, rlin_b, route);

    cudaEventRecord(ev2, s2);
    cudaStreamWaitEvent(0, ev2, 0);

    red_h<<<(Md*192 + 255)/256, 256>>>(hpart, route, h, 192);
    mma_gemm<<<dim3(24,32,1), 256, GEMM_SMEM>>>(h, Bt3f, Bt3f, Bt3f, -1, qkv,
        Md, 3072, 192, 192, 192, 3072,
        0,
        1.f, nullptr, nullptr, nullptr, nullptr, 1);

    attn_fused<<<dim3(8,64), 256, ATTN_SMEM>>>(qkv, qk, wv);

    cudaEventRecord(ev3, 0);
    cudaStreamWaitEvent(s2, ev3, 0);
    mma_gemm<<<dim3(1,32,4), 256, GEMM_SMEM, s2>>>(wv, oA, oA, oA, -1, hpart,
        Md, 64, 256, 1024, 1024, 64,
        (long long)Md*64,
        1.f, nullptr, nullptr, nullptr, nullptr, 0);
    red_h<<<(Md*64 + 255)/256, 256, 0, s2>>>(hpart, route, h, 64);

    mma_gemm<<<dim3(8,32,1), 256, GEMM_SMEM>>>(wv, oW, oW, oW, -1, out,
        Md, 1024, 1024, 1024, 1024, 1024,
        0,
        1.f, ob, nullptr, nullptr, nullptr, 0);

    cudaEventRecord(ev4, s2);
    cudaStreamWaitEvent(0, ev4, 0);

    mma_gemm<<<dim3(8,32,1), 256, GEMM_SMEM>>>(h, Bt, Bt, Bt, -1, out,
        Md, 1024, 64, 192, 64, 1024,
        0,
        1.f, nullptr, nullptr, nullptr, nullptr, 1);
}